// round 1
// baseline (speedup 1.0000x reference)
#include <cuda_runtime.h>
#include <cuda_bf16.h>
#include <math.h>

// ---------------- problem constants ----------------
#define BNB   650          // fused batch*node
#define TT    48
#define T2    12
#define VV    3
#define CC    128
#define DIN   387          // (C+1)*V
#define HD    512
#define HH    8
#define DD    64
#define LL    4
#define NB    6
#define NHID  4
#define CY    515
#define ROWS  (BNB*T2)     // 7800
#define KVROWS (BNB*TT)    // 31200
#define LOG2PI 1.8378770664093453f

// ---------------- scratch (static device memory; no allocs allowed) ----------
__device__ float g_ev[BNB*TT*DIN];              // [650,48,387]
__device__ float g_keys[LL*HH*BNB*TT*DD];       // [l][h][bn][t][d]
__device__ float g_vals[LL*HH*BNB*TT*DD];
__device__ float g_attin[ROWS*384];             // [7800,384]
__device__ float g_attv[ROWS*HD];               // [7800,512]
__device__ float g_attbuf[ROWS*HD];
__device__ float g_f1[ROWS*HD];
__device__ float g_f2[ROWS*HD];
__device__ float g_inp[ROWS*CY];                // [7800,515]
__device__ float g_h1[ROWS*HD];
__device__ float g_h2[ROWS*HD];
__device__ float g_snet[ROWS*VV];
__device__ float g_tnet[ROWS*VV];
__device__ float g_u[ROWS*VV];
__device__ float g_ld[ROWS*VV];
__device__ float g_stats[2*T2*VV];              // mean, var per (t2,v)

// ---------------- generic batched SGEMM: C = act(A@B + bias) ----------------
// A:[M,K] row-major (lda), B:[K,N] row-major, C:[M,N]. z batches B/bias/C.
#define BM 128
#define BN 64
#define BK 16
#define TM 8
#define TN 4

__global__ __launch_bounds__(256) void sgemm_kernel(
    const float* __restrict__ A, int lda,
    const float* __restrict__ B, const float* __restrict__ bias,
    float* __restrict__ C,
    int M, int N, int K, int act,
    long long sB, long long sBias, long long sC)
{
    __shared__ float As[BK][BM+4];
    __shared__ float Bs[BK][BN+4];
    long long z = blockIdx.z;
    B    += z * sB;
    bias += z * sBias;
    C    += z * sC;
    int bm = blockIdx.x * BM;
    int bn = blockIdx.y * BN;
    int tid = threadIdx.x;
    int tx = tid & 15, ty = tid >> 4;
    float acc[TM][TN];
    #pragma unroll
    for (int i = 0; i < TM; i++)
        #pragma unroll
        for (int j = 0; j < TN; j++) acc[i][j] = 0.f;

    int ar = tid >> 2;          // 0..63  (A rows; +64 for second half)
    int ac = (tid & 3) * 4;     // 0,4,8,12
    int br = tid >> 4;          // 0..15  (B k-row)
    int bc = (tid & 15) * 4;    // 0..60

    for (int k0 = 0; k0 < K; k0 += BK) {
        #pragma unroll
        for (int rr = 0; rr < 2; rr++) {
            int row = bm + ar + rr*64;
            const float* Ap = A + (long long)row * lda + k0 + ac;
            bool rowok = row < M;
            #pragma unroll
            for (int j = 0; j < 4; j++) {
                int kk = k0 + ac + j;
                As[ac + j][ar + rr*64] = (rowok && kk < K) ? Ap[j] : 0.f;
            }
        }
        {
            int kk = k0 + br;
            const float* Bp = B + (long long)kk * N + bn + bc;
            bool kok = kk < K;
            #pragma unroll
            for (int j = 0; j < 4; j++)
                Bs[br][bc + j] = (kok && (bn + bc + j) < N) ? Bp[j] : 0.f;
        }
        __syncthreads();
        #pragma unroll
        for (int k = 0; k < BK; k++) {
            float af[TM], bf[TN];
            #pragma unroll
            for (int i = 0; i < TM; i++) af[i] = As[k][ty*TM + i];
            #pragma unroll
            for (int j = 0; j < TN; j++) bf[j] = Bs[k][tx*TN + j];
            #pragma unroll
            for (int i = 0; i < TM; i++)
                #pragma unroll
                for (int j = 0; j < TN; j++)
                    acc[i][j] += af[i] * bf[j];
        }
        __syncthreads();
    }
    #pragma unroll
    for (int i = 0; i < TM; i++) {
        int row = bm + ty*TM + i;
        if (row >= M) continue;
        #pragma unroll
        for (int j = 0; j < TN; j++) {
            int col = bn + tx*TN + j;
            if (col >= N) continue;
            float v = acc[i][j] + bias[col];
            if (act == 1) v = fmaxf(v, 0.f);
            else if (act == 2) v = tanhf(v);
            C[(long long)row * N + col] = v;
        }
    }
}

// ---------------- elementwise / gather kernels ----------------
__global__ void build_ev_kernel(const float* __restrict__ encoded,
                                const float* __restrict__ tv)
{
    int idx = blockIdx.x * blockDim.x + threadIdx.x;
    if (idx >= BNB*TT*DIN) return;
    int bn = idx / (TT*DIN);
    int rem = idx - bn * (TT*DIN);
    int t = rem / DIN;
    int e = rem - t * DIN;
    int v = e / (CC+1);
    int j = e - v * (CC+1);
    float val;
    if (j < CC) val = encoded[(((long long)bn*VV + v)*TT + t)*CC + j];
    else        val = tv[((long long)bn*VV + v)*TT + t];
    g_ev[idx] = val;
}

__global__ void build_attin_kernel(const float* __restrict__ encoded)
{
    int idx = blockIdx.x * blockDim.x + threadIdx.x;
    if (idx >= ROWS*384) return;
    int row = idx / 384;           // bn*12 + t2
    int col = idx - row*384;
    int bn = row / T2, t2 = row - bn*T2;
    int v = col >> 7, j = col & 127;
    g_attin[idx] = encoded[(((long long)bn*VV + v)*TT + (TT - T2 + t2))*CC + j];
}

// attention for one layer: grid (650, 8), 256 threads
__global__ void attn_kernel(const float* __restrict__ attv,
                            const float* __restrict__ keys_l,
                            const float* __restrict__ vals_l,
                            float* __restrict__ attbuf)
{
    int bn = blockIdx.x, h = blockIdx.y;
    __shared__ float Qs[T2*DD];
    __shared__ float Ks[TT*DD];
    __shared__ float Vs[TT*DD];
    __shared__ float Ss[T2*TT];
    int tid = threadIdx.x;
    const float* kb = keys_l + ((long long)h*BNB + bn) * (TT*DD);
    const float* vb = vals_l + ((long long)h*BNB + bn) * (TT*DD);
    for (int i = tid; i < TT*DD; i += 256) { Ks[i] = kb[i]; Vs[i] = vb[i]; }
    for (int i = tid; i < T2*DD; i += 256) {
        int v = i >> 6, d = i & 63;
        Qs[i] = attv[((long long)bn*T2 + v)*HD + h*DD + d];
    }
    __syncthreads();
    const float scale = 0.125f;
    for (int i = tid; i < T2*TT; i += 256) {
        int v = i / TT, w = i - v*TT;
        float s;
        if (w >= (TT - T2) + v) s = -INFINITY;
        else {
            float a = 0.f;
            #pragma unroll
            for (int d = 0; d < DD; d++) a += Qs[v*DD+d] * Ks[w*DD+d];
            s = a * scale;
        }
        Ss[i] = s;
    }
    __syncthreads();
    if (tid < T2) {
        int v = tid;
        float m = -INFINITY;
        for (int w = 0; w < TT; w++) m = fmaxf(m, Ss[v*TT+w]);
        float sum = 0.f;
        for (int w = 0; w < TT; w++) {
            float e = expf(Ss[v*TT+w] - m);
            Ss[v*TT+w] = e; sum += e;
        }
        float inv = 1.f / sum;
        for (int w = 0; w < TT; w++) Ss[v*TT+w] *= inv;
    }
    __syncthreads();
    for (int i = tid; i < T2*DD; i += 256) {
        int v = i >> 6, d = i & 63;
        float a = 0.f;
        #pragma unroll
        for (int w = 0; w < TT; w++) a += Ss[v*TT+w] * Vs[w*DD+d];
        attbuf[((long long)bn*T2 + v)*HD + h*DD + d] = a;
    }
}

// x = LN(x + r) per row of 512, with scale/shift
__global__ void add_ln_kernel(float* __restrict__ x, const float* __restrict__ r,
                              const float* __restrict__ g, const float* __restrict__ b)
{
    int row = blockIdx.x;
    int tid = threadIdx.x;  // 256
    __shared__ float red[256];
    long long base = (long long)row * HD;
    float v0 = x[base + tid] + r[base + tid];
    float v1 = x[base + tid + 256] + r[base + tid + 256];
    red[tid] = v0 + v1;
    __syncthreads();
    for (int s = 128; s > 0; s >>= 1) { if (tid < s) red[tid] += red[tid+s]; __syncthreads(); }
    float mean = red[0] * (1.f/512.f);
    __syncthreads();
    float d0 = v0 - mean, d1 = v1 - mean;
    red[tid] = d0*d0 + d1*d1;
    __syncthreads();
    for (int s = 128; s > 0; s >>= 1) { if (tid < s) red[tid] += red[tid+s]; __syncthreads(); }
    float rstd = rsqrtf(red[0] * (1.f/512.f) + 1e-5f);
    x[base + tid]       = d0 * rstd * g[tid]       + b[tid];
    x[base + tid + 256] = d1 * rstd * g[tid + 256] + b[tid + 256];
}

__global__ void init_flow_kernel(const float* __restrict__ tv)
{
    int idx = blockIdx.x * blockDim.x + threadIdx.x;
    if (idx >= ROWS*VV) return;
    int bn = idx / (T2*VV);
    int rem = idx - bn * (T2*VV);
    int t2 = rem / VV, v = rem - t2*VV;
    g_u[idx] = tv[((long long)bn*VV + v)*TT + (TT - T2 + t2)];
    g_ld[idx] = 0.f;
}

__global__ void copy_y_kernel()
{
    int idx = blockIdx.x * blockDim.x + threadIdx.x;
    if (idx >= ROWS*HD) return;
    int row = idx >> 9, col = idx & 511;
    g_inp[(long long)row * CY + col] = g_attv[idx];
}

__global__ void write_mu_kernel(int blk)
{
    int idx = blockIdx.x * blockDim.x + threadIdx.x;
    if (idx >= ROWS*VV) return;
    int row = idx / VV, v = idx - row*VV;
    float mask = (float)((v + blk) & 1);
    g_inp[(long long)row * CY + HD + v] = g_u[idx] * mask;
}

// out3: C[7800,3] = A[7800,512] @ W[512,3] + bias; one warp per row
__global__ void gemm_out3_kernel(const float* __restrict__ A, const float* __restrict__ W,
                                 const float* __restrict__ bias, float* __restrict__ out)
{
    int gw = (blockIdx.x * blockDim.x + threadIdx.x) >> 5;
    int lane = threadIdx.x & 31;
    if (gw >= ROWS) return;
    const float* a = A + (long long)gw * HD;
    float s0 = 0.f, s1 = 0.f, s2 = 0.f;
    for (int k = lane; k < HD; k += 32) {
        float av = a[k];
        s0 += av * W[k*3 + 0];
        s1 += av * W[k*3 + 1];
        s2 += av * W[k*3 + 2];
    }
    #pragma unroll
    for (int off = 16; off > 0; off >>= 1) {
        s0 += __shfl_down_sync(0xffffffffu, s0, off);
        s1 += __shfl_down_sync(0xffffffffu, s1, off);
        s2 += __shfl_down_sync(0xffffffffu, s2, off);
    }
    if (lane == 0) {
        out[gw*3 + 0] = s0 + bias[0];
        out[gw*3 + 1] = s1 + bias[1];
        out[gw*3 + 2] = s2 + bias[2];
    }
}

__global__ void coupling_kernel(int blk)
{
    int idx = blockIdx.x * blockDim.x + threadIdx.x;
    if (idx >= ROWS*VV) return;
    int v = idx % VV;
    if (((v + blk) & 1) == 0) {
        float s = g_snet[idx];
        g_u[idx] = (g_u[idx] - g_tnet[idx]) * expf(-s);
        g_ld[idx] -= s;
    }
}

__global__ void bn_stats_kernel()
{
    int col = blockIdx.x;   // 0..35 = t2*3+v
    int tid = threadIdx.x;  // 256
    __shared__ float rs[256], rq[256];
    float s = 0.f, q = 0.f;
    for (int bn = tid; bn < BNB; bn += 256) {
        float v = g_u[bn*(T2*VV) + col];
        s += v; q += v*v;
    }
    rs[tid] = s; rq[tid] = q;
    __syncthreads();
    for (int st = 128; st > 0; st >>= 1) {
        if (tid < st) { rs[tid] += rs[tid+st]; rq[tid] += rq[tid+st]; }
        __syncthreads();
    }
    if (tid == 0) {
        float m = rs[0] / (float)BNB;
        float var = rq[0] / (float)BNB - m*m;
        g_stats[col] = m;
        g_stats[T2*VV + col] = fmaxf(var, 0.f);
    }
}

__global__ void bn_apply_kernel(const float* __restrict__ lg,
                                const float* __restrict__ beta, int blk)
{
    int idx = blockIdx.x * blockDim.x + threadIdx.x;
    if (idx >= ROWS*VV) return;
    int col = idx % (T2*VV);
    int v = idx % VV;
    float m = g_stats[col];
    float var = g_stats[T2*VV + col];
    float gg = lg[blk*VV + v];
    float be = beta[blk*VV + v];
    float r = rsqrtf(var + 1e-5f);
    g_u[idx] = expf(gg) * (g_u[idx] - m) * r + be;
    g_ld[idx] += gg - 0.5f * logf(var + 1e-5f);
}

__global__ void final_kernel(float* __restrict__ out)
{
    int bn = blockIdx.x * blockDim.x + threadIdx.x;
    if (bn >= BNB) return;
    float acc = 0.f;
    #pragma unroll
    for (int i = 0; i < T2*VV; i++) {
        float u = g_u[bn*(T2*VV) + i];
        acc += 0.5f*u*u + 0.5f*LOG2PI - g_ld[bn*(T2*VV) + i];
    }
    out[bn] = acc;
}

// ---------------- host launcher ----------------
static inline void run_gemm(const float* A, int lda, const float* B, const float* bias,
                            float* C, int M, int N, int K, int act,
                            long long sB, long long sBias, long long sC, int Z)
{
    dim3 grid((M + BM - 1)/BM, (N + BN - 1)/BN, Z);
    sgemm_kernel<<<grid, 256>>>(A, lda, B, bias, C, M, N, K, act, sB, sBias, sC);
}

extern "C" void kernel_launch(void* const* d_in, const int* in_sizes, int n_in,
                              void* d_out, int out_size)
{
    const float* encoded    = (const float*)d_in[0];
    const float* true_value = (const float*)d_in[1];
    const float* W_shift    = (const float*)d_in[2];
    const float* b_shift    = (const float*)d_in[3];
    const float* W_key      = (const float*)d_in[4];
    const float* b_key      = (const float*)d_in[5];
    const float* W_val      = (const float*)d_in[6];
    const float* b_val      = (const float*)d_in[7];
    const float* ln1_s      = (const float*)d_in[8];
    const float* ln1_b      = (const float*)d_in[9];
    const float* ff_w1      = (const float*)d_in[10];
    const float* ff_b1      = (const float*)d_in[11];
    const float* ff_w2      = (const float*)d_in[12];
    const float* ff_b2      = (const float*)d_in[13];
    const float* ln2_s      = (const float*)d_in[14];
    const float* ln2_b      = (const float*)d_in[15];
    const float* s_w_in     = (const float*)d_in[16];
    const float* s_b_in     = (const float*)d_in[17];
    const float* s_w_hid    = (const float*)d_in[18];
    const float* s_b_hid    = (const float*)d_in[19];
    const float* s_w_out    = (const float*)d_in[20];
    const float* s_b_out    = (const float*)d_in[21];
    const float* t_w_in     = (const float*)d_in[22];
    const float* t_b_in     = (const float*)d_in[23];
    const float* t_w_hid    = (const float*)d_in[24];
    const float* t_b_hid    = (const float*)d_in[25];
    const float* t_w_out    = (const float*)d_in[26];
    const float* t_b_out    = (const float*)d_in[27];
    const float* bn_lg      = (const float*)d_in[28];
    const float* bn_be      = (const float*)d_in[29];
    float* out = (float*)d_out;

    float *ev, *keys, *vals, *attin, *attv, *attbuf, *f1, *f2, *inp, *h1, *h2, *snet, *tnet;
    cudaGetSymbolAddress((void**)&ev,     g_ev);
    cudaGetSymbolAddress((void**)&keys,   g_keys);
    cudaGetSymbolAddress((void**)&vals,   g_vals);
    cudaGetSymbolAddress((void**)&attin,  g_attin);
    cudaGetSymbolAddress((void**)&attv,   g_attv);
    cudaGetSymbolAddress((void**)&attbuf, g_attbuf);
    cudaGetSymbolAddress((void**)&f1,     g_f1);
    cudaGetSymbolAddress((void**)&f2,     g_f2);
    cudaGetSymbolAddress((void**)&inp,    g_inp);
    cudaGetSymbolAddress((void**)&h1,     g_h1);
    cudaGetSymbolAddress((void**)&h2,     g_h2);
    cudaGetSymbolAddress((void**)&snet,   g_snet);
    cudaGetSymbolAddress((void**)&tnet,   g_tnet);

    // 1) encoded_value gather
    {
        int n = BNB*TT*DIN;
        build_ev_kernel<<<(n + 255)/256, 256>>>(encoded, true_value);
    }
    // 2) K/V projections: 32 batched GEMMs each (z = l*8+h)
    run_gemm(ev, DIN, W_key, b_key, keys, KVROWS, DD, DIN, 0,
             (long long)DIN*DD, DD, (long long)BNB*TT*DD, LL*HH);
    run_gemm(ev, DIN, W_val, b_val, vals, KVROWS, DD, DIN, 0,
             (long long)DIN*DD, DD, (long long)BNB*TT*DD, LL*HH);
    // 3) query path
    {
        int n = ROWS*384;
        build_attin_kernel<<<(n + 255)/256, 256>>>(encoded);
    }
    run_gemm(attin, 384, W_shift, b_shift, attv, ROWS, HD, 384, 0, 0, 0, 0, 1);
    // 4) transformer layers
    for (int l = 0; l < LL; l++) {
        attn_kernel<<<dim3(BNB, HH), 256>>>(attv,
            keys + (long long)l*HH*BNB*TT*DD,
            vals + (long long)l*HH*BNB*TT*DD, attbuf);
        add_ln_kernel<<<ROWS, 256>>>(attv, attbuf, ln1_s + l*HD, ln1_b + l*HD);
        run_gemm(attv, HD, ff_w1 + (long long)l*HD*HD, ff_b1 + l*HD, f1,
                 ROWS, HD, HD, 1, 0, 0, 0, 1);
        run_gemm(f1, HD, ff_w2 + (long long)l*HD*HD, ff_b2 + l*HD, f2,
                 ROWS, HD, HD, 0, 0, 0, 0, 1);
        add_ln_kernel<<<ROWS, 256>>>(attv, f2, ln2_s + l*HD, ln2_b + l*HD);
    }
    // 5) RealNVP flow
    {
        int n = ROWS*VV;
        init_flow_kernel<<<(n + 255)/256, 256>>>(true_value);
        int n2 = ROWS*HD;
        copy_y_kernel<<<(n2 + 255)/256, 256>>>();
    }
    for (int blk = 0; blk < NB; blk++) {
        {
            int n = ROWS*VV;
            write_mu_kernel<<<(n + 255)/256, 256>>>(blk);
        }
        // --- s net (tanh) ---
        run_gemm(inp, CY, s_w_in + (long long)blk*CY*HD, s_b_in + blk*HD, h1,
                 ROWS, HD, CY, 2, 0, 0, 0, 1);
        {
            float* bufs[5] = {h1, h2, h1, h2, h1};
            for (int i = 0; i < NHID; i++) {
                run_gemm(bufs[i], HD, s_w_hid + (long long)(blk*NHID + i)*HD*HD,
                         s_b_hid + (long long)(blk*NHID + i)*HD, bufs[i+1],
                         ROWS, HD, HD, 2, 0, 0, 0, 1);
            }
            gemm_out3_kernel<<<(ROWS*32 + 255)/256, 256>>>(bufs[NHID],
                s_w_out + (long long)blk*HD*VV, s_b_out + blk*VV, snet);
        }
        // --- t net (relu) ---
        run_gemm(inp, CY, t_w_in + (long long)blk*CY*HD, t_b_in + blk*HD, h1,
                 ROWS, HD, CY, 1, 0, 0, 0, 1);
        {
            float* bufs[5] = {h1, h2, h1, h2, h1};
            for (int i = 0; i < NHID; i++) {
                run_gemm(bufs[i], HD, t_w_hid + (long long)(blk*NHID + i)*HD*HD,
                         t_b_hid + (long long)(blk*NHID + i)*HD, bufs[i+1],
                         ROWS, HD, HD, 1, 0, 0, 0, 1);
            }
            gemm_out3_kernel<<<(ROWS*32 + 255)/256, 256>>>(bufs[NHID],
                t_w_out + (long long)blk*HD*VV, t_b_out + blk*VV, tnet);
        }
        {
            int n = ROWS*VV;
            coupling_kernel<<<(n + 255)/256, 256>>>(blk);
            bn_stats_kernel<<<T2*VV, 256>>>();
            bn_apply_kernel<<<(n + 255)/256, 256>>>(bn_lg, bn_be, blk);
        }
    }
    // 6) final log-prob reduction
    final_kernel<<<(BNB + 255)/256, 256>>>(out);
}

// round 3
// speedup vs baseline: 2.0449x; 2.0449x over previous
#include <cuda_runtime.h>
#include <mma.h>
#include <cstdint>
#include <math.h>

using namespace nvcuda;

// ---------------- problem constants ----------------
#define BNB   650
#define TT    48
#define T2    12
#define VV    3
#define CC    128
#define DIN   387
#define HD    512
#define HH    8
#define DD    64
#define LL    4
#define NB    6
#define NHID  4
#define CY    515
#define ROWS  (BNB*T2)     // 7800
#define KVROWS (BNB*TT)    // 31200
#define LOG2PI 1.8378770664093453f

// ---------------- scratch ----------------
__device__ float g_ev[BNB*TT*DIN];
__device__ float g_wk[LL*DIN*HD];
__device__ float g_wv[LL*DIN*HD];
__device__ float g_keys[LL*KVROWS*HD];         // [l][bn*48+t][h*64+d]
__device__ float g_vals[LL*KVROWS*HD];
__device__ float g_attin[ROWS*384];
__device__ float g_attv[ROWS*HD];
__device__ float g_attbuf[ROWS*HD];
__device__ float g_f1[ROWS*HD];
__device__ float g_f2[ROWS*HD];
__device__ float g_inp[ROWS*CY];
__device__ float g_h1[ROWS*HD];
__device__ float g_h2[ROWS*HD];
__device__ float g_snet[ROWS*VV];
__device__ float g_tnet[ROWS*VV];
__device__ float g_u[ROWS*VV];
__device__ float g_ld[ROWS*VV];
__device__ float g_stats[2*T2*VV];

__device__ __forceinline__ float epi_act(float v, int act) {
    if (act == 1) return fmaxf(v, 0.f);
    if (act == 2) return tanhf(v);
    return v;
}

// ---------------- wmma tf32 GEMM ----------------
// C[M,N] = act(A[M,K] @ B[K,N] + bias). 128x128 CTA tile, 8 warps of 32x64.
// SMEM: A chunk [128][36], B chunk [32][132]; C staging [128][132] (overlaps).
#define ALD 36
#define BLD 132
#define A_ELEMS (128*ALD)              // 4608
#define WM_SMEM (128*BLD*4)            // 67584 bytes (C staging dominates)

__global__ __launch_bounds__(256) void wmma_gemm(
    const float* __restrict__ A, int lda,
    const float* __restrict__ B, const float* __restrict__ bias,
    float* __restrict__ C, int M, int N, int K, int act,
    long long sB, long long sBias, long long sC)
{
    extern __shared__ float sm[];
    float* As = sm;                    // [128][36]
    float* Bs = sm + A_ELEMS;          // [32][132]
    float* Cs = sm;                    // [128][132] (reused after K loop)

    long long z = blockIdx.z;
    B    += z * sB;
    bias += z * sBias;
    C    += z * sC;
    int bm = blockIdx.x * 128, bn = blockIdx.y * 128;
    int tid = threadIdx.x, wid = tid >> 5;
    int warp_m = wid >> 1;             // 0..3  (rows 32*warp_m)
    int warp_n = wid & 1;              // 0..1  (cols 64*warp_n)

    wmma::fragment<wmma::accumulator, 16, 16, 8, float> acc[2][4];
    #pragma unroll
    for (int i = 0; i < 2; i++)
        #pragma unroll
        for (int j = 0; j < 4; j++) wmma::fill_fragment(acc[i][j], 0.f);

    int nchunks = (K + 31) >> 5;
    for (int c = 0; c < nchunks; c++) {
        int k0c = c << 5;
        // A chunk [128 x 32]
        #pragma unroll
        for (int it = 0; it < 16; it++) {
            int i = it * 256 + tid;
            int r = i >> 5, kk = i & 31;
            int gm = bm + r, gk = k0c + kk;
            As[r * ALD + kk] = (gm < M && gk < K) ? A[(long long)gm * lda + gk] : 0.f;
        }
        // B chunk [32 x 128]
        #pragma unroll
        for (int it = 0; it < 16; it++) {
            int i = it * 256 + tid;
            int kk = i >> 7, n = i & 127;
            int gk = k0c + kk, gn = bn + n;
            Bs[kk * BLD + n] = (gk < K && gn < N) ? B[(long long)gk * N + gn] : 0.f;
        }
        __syncthreads();
        #pragma unroll
        for (int ks = 0; ks < 4; ks++) {
            int k0 = ks * 8;
            wmma::fragment<wmma::matrix_a, 16, 16, 8, wmma::precision::tf32, wmma::row_major> af[2];
            wmma::fragment<wmma::matrix_b, 16, 16, 8, wmma::precision::tf32, wmma::row_major> bf[4];
            #pragma unroll
            for (int i = 0; i < 2; i++) {
                wmma::load_matrix_sync(af[i], As + (warp_m*32 + i*16) * ALD + k0, ALD);
                #pragma unroll
                for (int t = 0; t < af[i].num_elements; t++)
                    af[i].x[t] = wmma::__float_to_tf32(af[i].x[t]);
            }
            #pragma unroll
            for (int j = 0; j < 4; j++) {
                wmma::load_matrix_sync(bf[j], Bs + k0 * BLD + warp_n*64 + j*16, BLD);
                #pragma unroll
                for (int t = 0; t < bf[j].num_elements; t++)
                    bf[j].x[t] = wmma::__float_to_tf32(bf[j].x[t]);
            }
            #pragma unroll
            for (int i = 0; i < 2; i++)
                #pragma unroll
                for (int j = 0; j < 4; j++)
                    wmma::mma_sync(acc[i][j], af[i], bf[j], acc[i][j]);
        }
        __syncthreads();
    }

    // stage C in smem, then fused bias+act write
    #pragma unroll
    for (int i = 0; i < 2; i++)
        #pragma unroll
        for (int j = 0; j < 4; j++)
            wmma::store_matrix_sync(Cs + (warp_m*32 + i*16) * BLD + warp_n*64 + j*16,
                                    acc[i][j], BLD, wmma::mem_row_major);
    __syncthreads();

    // epilogue: 4096 float4 / 256 threads = 16 iters
    #pragma unroll
    for (int it = 0; it < 16; it++) {
        int idx = it * 256 + tid;           // float4 index
        int r = idx >> 5, c4 = (idx & 31) * 4;
        int gm = bm + r;
        if (gm >= M) continue;
        int gc = bn + c4;
        float4 v;
        v.x = epi_act(Cs[r * BLD + c4 + 0] + bias[gc + 0], act);
        v.y = epi_act(Cs[r * BLD + c4 + 1] + bias[gc + 1], act);
        v.z = epi_act(Cs[r * BLD + c4 + 2] + bias[gc + 2], act);
        v.w = epi_act(Cs[r * BLD + c4 + 3] + bias[gc + 3], act);
        *(float4*)(C + (long long)gm * N + gc) = v;
    }
}

// ---------------- small kernels ----------------
__global__ void transpose_w_kernel(const float* __restrict__ W, float* __restrict__ out)
{
    int idx = blockIdx.x * blockDim.x + threadIdx.x;
    if (idx >= LL*DIN*HD) return;
    int l = idx / (DIN*HD);
    int rem = idx - l * (DIN*HD);
    int e = rem / HD;
    int n = rem - e * HD;
    int h = n >> 6, d = n & 63;
    out[idx] = W[(((long long)l*HH + h)*DIN + e)*DD + d];
}

__global__ void build_ev_kernel(const float* __restrict__ encoded,
                                const float* __restrict__ tv)
{
    int idx = blockIdx.x * blockDim.x + threadIdx.x;
    if (idx >= BNB*TT*DIN) return;
    int bn = idx / (TT*DIN);
    int rem = idx - bn * (TT*DIN);
    int t = rem / DIN;
    int e = rem - t * DIN;
    int v = e / (CC+1);
    int j = e - v * (CC+1);
    float val;
    if (j < CC) val = encoded[(((long long)bn*VV + v)*TT + t)*CC + j];
    else        val = tv[((long long)bn*VV + v)*TT + t];
    g_ev[idx] = val;
}

__global__ void build_attin_kernel(const float* __restrict__ encoded)
{
    int idx = blockIdx.x * blockDim.x + threadIdx.x;
    if (idx >= ROWS*384) return;
    int row = idx / 384;
    int col = idx - row*384;
    int bn = row / T2, t2 = row - bn*T2;
    int v = col >> 7, j = col & 127;
    g_attin[idx] = encoded[(((long long)bn*VV + v)*TT + (TT - T2 + t2))*CC + j];
}

__global__ void attn_kernel(const float* __restrict__ attv,
                            const float* __restrict__ keys_l,
                            const float* __restrict__ vals_l,
                            float* __restrict__ attbuf)
{
    int bn = blockIdx.x, h = blockIdx.y;
    __shared__ float Qs[T2*DD];
    __shared__ float Ks[TT*DD];
    __shared__ float Vs[TT*DD];
    __shared__ float Ss[T2*TT];
    int tid = threadIdx.x;
    const float* kb = keys_l + (long long)bn*TT*HD + h*DD;
    const float* vb = vals_l + (long long)bn*TT*HD + h*DD;
    for (int i = tid; i < TT*DD; i += 256) {
        int t = i >> 6, d = i & 63;
        Ks[i] = kb[(long long)t*HD + d];
        Vs[i] = vb[(long long)t*HD + d];
    }
    for (int i = tid; i < T2*DD; i += 256) {
        int v = i >> 6, d = i & 63;
        Qs[i] = attv[((long long)bn*T2 + v)*HD + h*DD + d];
    }
    __syncthreads();
    const float scale = 0.125f;
    for (int i = tid; i < T2*TT; i += 256) {
        int v = i / TT, w = i - v*TT;
        float s;
        if (w >= (TT - T2) + v) s = -INFINITY;
        else {
            float a = 0.f;
            #pragma unroll
            for (int d = 0; d < DD; d++) a += Qs[v*DD+d] * Ks[w*DD+d];
            s = a * scale;
        }
        Ss[i] = s;
    }
    __syncthreads();
    if (tid < T2) {
        int v = tid;
        float m = -INFINITY;
        for (int w = 0; w < TT; w++) m = fmaxf(m, Ss[v*TT+w]);
        float sum = 0.f;
        for (int w = 0; w < TT; w++) {
            float e = expf(Ss[v*TT+w] - m);
            Ss[v*TT+w] = e; sum += e;
        }
        float inv = 1.f / sum;
        for (int w = 0; w < TT; w++) Ss[v*TT+w] *= inv;
    }
    __syncthreads();
    for (int i = tid; i < T2*DD; i += 256) {
        int v = i >> 6, d = i & 63;
        float a = 0.f;
        #pragma unroll
        for (int w = 0; w < TT; w++) a += Ss[v*TT+w] * Vs[w*DD+d];
        attbuf[((long long)bn*T2 + v)*HD + h*DD + d] = a;
    }
}

__global__ void add_ln_kernel(float* __restrict__ x, const float* __restrict__ r,
                              const float* __restrict__ g, const float* __restrict__ b)
{
    int row = blockIdx.x;
    int tid = threadIdx.x;
    __shared__ float red[256];
    long long base = (long long)row * HD;
    float v0 = x[base + tid] + r[base + tid];
    float v1 = x[base + tid + 256] + r[base + tid + 256];
    red[tid] = v0 + v1;
    __syncthreads();
    for (int s = 128; s > 0; s >>= 1) { if (tid < s) red[tid] += red[tid+s]; __syncthreads(); }
    float mean = red[0] * (1.f/512.f);
    __syncthreads();
    float d0 = v0 - mean, d1 = v1 - mean;
    red[tid] = d0*d0 + d1*d1;
    __syncthreads();
    for (int s = 128; s > 0; s >>= 1) { if (tid < s) red[tid] += red[tid+s]; __syncthreads(); }
    float rstd = rsqrtf(red[0] * (1.f/512.f) + 1e-5f);
    x[base + tid]       = d0 * rstd * g[tid]       + b[tid];
    x[base + tid + 256] = d1 * rstd * g[tid + 256] + b[tid + 256];
}

__global__ void init_flow_kernel(const float* __restrict__ tv)
{
    int idx = blockIdx.x * blockDim.x + threadIdx.x;
    if (idx >= ROWS*VV) return;
    int bn = idx / (T2*VV);
    int rem = idx - bn * (T2*VV);
    int t2 = rem / VV, v = rem - t2*VV;
    g_u[idx] = tv[((long long)bn*VV + v)*TT + (TT - T2 + t2)];
    g_ld[idx] = 0.f;
}

__global__ void copy_y_kernel()
{
    int idx = blockIdx.x * blockDim.x + threadIdx.x;
    if (idx >= ROWS*HD) return;
    int row = idx >> 9, col = idx & 511;
    g_inp[(long long)row * CY + col] = g_attv[idx];
}

__global__ void write_mu_kernel(int blk)
{
    int idx = blockIdx.x * blockDim.x + threadIdx.x;
    if (idx >= ROWS*VV) return;
    int row = idx / VV, v = idx - row*VV;
    float mask = (float)((v + blk) & 1);
    g_inp[(long long)row * CY + HD + v] = g_u[idx] * mask;
}

__global__ void gemm_out3_kernel(const float* __restrict__ A, const float* __restrict__ W,
                                 const float* __restrict__ bias, float* __restrict__ out)
{
    int gw = (blockIdx.x * blockDim.x + threadIdx.x) >> 5;
    int lane = threadIdx.x & 31;
    if (gw >= ROWS) return;
    const float* a = A + (long long)gw * HD;
    float s0 = 0.f, s1 = 0.f, s2 = 0.f;
    for (int k = lane; k < HD; k += 32) {
        float av = a[k];
        s0 += av * W[k*3 + 0];
        s1 += av * W[k*3 + 1];
        s2 += av * W[k*3 + 2];
    }
    #pragma unroll
    for (int off = 16; off > 0; off >>= 1) {
        s0 += __shfl_down_sync(0xffffffffu, s0, off);
        s1 += __shfl_down_sync(0xffffffffu, s1, off);
        s2 += __shfl_down_sync(0xffffffffu, s2, off);
    }
    if (lane == 0) {
        out[gw*3 + 0] = s0 + bias[0];
        out[gw*3 + 1] = s1 + bias[1];
        out[gw*3 + 2] = s2 + bias[2];
    }
}

__global__ void coupling_kernel(int blk)
{
    int idx = blockIdx.x * blockDim.x + threadIdx.x;
    if (idx >= ROWS*VV) return;
    int v = idx % VV;
    if (((v + blk) & 1) == 0) {
        float s = g_snet[idx];
        g_u[idx] = (g_u[idx] - g_tnet[idx]) * expf(-s);
        g_ld[idx] -= s;
    }
}

__global__ void bn_stats_kernel()
{
    int col = blockIdx.x;
    int tid = threadIdx.x;
    __shared__ float rs[256], rq[256];
    float s = 0.f, q = 0.f;
    for (int bn = tid; bn < BNB; bn += 256) {
        float v = g_u[bn*(T2*VV) + col];
        s += v; q += v*v;
    }
    rs[tid] = s; rq[tid] = q;
    __syncthreads();
    for (int st = 128; st > 0; st >>= 1) {
        if (tid < st) { rs[tid] += rs[tid+st]; rq[tid] += rq[tid+st]; }
        __syncthreads();
    }
    if (tid == 0) {
        float m = rs[0] / (float)BNB;
        float var = rq[0] / (float)BNB - m*m;
        g_stats[col] = m;
        g_stats[T2*VV + col] = fmaxf(var, 0.f);
    }
}

__global__ void bn_apply_kernel(const float* __restrict__ lg,
                                const float* __restrict__ beta, int blk)
{
    int idx = blockIdx.x * blockDim.x + threadIdx.x;
    if (idx >= ROWS*VV) return;
    int col = idx % (T2*VV);
    int v = idx % VV;
    float m = g_stats[col];
    float var = g_stats[T2*VV + col];
    float gg = lg[blk*VV + v];
    float be = beta[blk*VV + v];
    float r = rsqrtf(var + 1e-5f);
    g_u[idx] = expf(gg) * (g_u[idx] - m) * r + be;
    g_ld[idx] += gg - 0.5f * logf(var + 1e-5f);
}

__global__ void final_kernel(float* __restrict__ out)
{
    int bn = blockIdx.x * blockDim.x + threadIdx.x;
    if (bn >= BNB) return;
    float acc = 0.f;
    #pragma unroll
    for (int i = 0; i < T2*VV; i++) {
        float u = g_u[bn*(T2*VV) + i];
        acc += 0.5f*u*u + 0.5f*LOG2PI - g_ld[bn*(T2*VV) + i];
    }
    out[bn] = acc;
}

// ---------------- host launcher ----------------
static inline void tcg(const float* A, int lda, const float* B, const float* bias,
                       float* C, int M, int N, int K, int act,
                       long long sB, long long sBias, long long sC, int Z)
{
    dim3 grid((M + 127)/128, N/128, Z);
    wmma_gemm<<<grid, 256, WM_SMEM>>>(A, lda, B, bias, C, M, N, K, act, sB, sBias, sC);
}

extern "C" void kernel_launch(void* const* d_in, const int* in_sizes, int n_in,
                              void* d_out, int out_size)
{
    const float* encoded    = (const float*)d_in[0];
    const float* true_value = (const float*)d_in[1];
    const float* W_shift    = (const float*)d_in[2];
    const float* b_shift    = (const float*)d_in[3];
    const float* W_key      = (const float*)d_in[4];
    const float* b_key      = (const float*)d_in[5];
    const float* W_val      = (const float*)d_in[6];
    const float* b_val      = (const float*)d_in[7];
    const float* ln1_s      = (const float*)d_in[8];
    const float* ln1_b      = (const float*)d_in[9];
    const float* ff_w1      = (const float*)d_in[10];
    const float* ff_b1      = (const float*)d_in[11];
    const float* ff_w2      = (const float*)d_in[12];
    const float* ff_b2      = (const float*)d_in[13];
    const float* ln2_s      = (const float*)d_in[14];
    const float* ln2_b      = (const float*)d_in[15];
    const float* s_w_in     = (const float*)d_in[16];
    const float* s_b_in     = (const float*)d_in[17];
    const float* s_w_hid    = (const float*)d_in[18];
    const float* s_b_hid    = (const float*)d_in[19];
    const float* s_w_out    = (const float*)d_in[20];
    const float* s_b_out    = (const float*)d_in[21];
    const float* t_w_in     = (const float*)d_in[22];
    const float* t_b_in     = (const float*)d_in[23];
    const float* t_w_hid    = (const float*)d_in[24];
    const float* t_b_hid    = (const float*)d_in[25];
    const float* t_w_out    = (const float*)d_in[26];
    const float* t_b_out    = (const float*)d_in[27];
    const float* bn_lg      = (const float*)d_in[28];
    const float* bn_be      = (const float*)d_in[29];
    float* out = (float*)d_out;

    cudaFuncSetAttribute(wmma_gemm, cudaFuncAttributeMaxDynamicSharedMemorySize, WM_SMEM);

    float *ev, *wk, *wv, *keys, *vals, *attin, *attv, *attbuf, *f1, *f2, *inp, *h1, *h2, *snet, *tnet;
    cudaGetSymbolAddress((void**)&ev,     g_ev);
    cudaGetSymbolAddress((void**)&wk,     g_wk);
    cudaGetSymbolAddress((void**)&wv,     g_wv);
    cudaGetSymbolAddress((void**)&keys,   g_keys);
    cudaGetSymbolAddress((void**)&vals,   g_vals);
    cudaGetSymbolAddress((void**)&attin,  g_attin);
    cudaGetSymbolAddress((void**)&attv,   g_attv);
    cudaGetSymbolAddress((void**)&attbuf, g_attbuf);
    cudaGetSymbolAddress((void**)&f1,     g_f1);
    cudaGetSymbolAddress((void**)&f2,     g_f2);
    cudaGetSymbolAddress((void**)&inp,    g_inp);
    cudaGetSymbolAddress((void**)&h1,     g_h1);
    cudaGetSymbolAddress((void**)&h2,     g_h2);
    cudaGetSymbolAddress((void**)&snet,   g_snet);
    cudaGetSymbolAddress((void**)&tnet,   g_tnet);

    {
        int n = LL*DIN*HD;
        transpose_w_kernel<<<(n + 255)/256, 256>>>(W_key, wk);
        transpose_w_kernel<<<(n + 255)/256, 256>>>(W_val, wv);
        int m = BNB*TT*DIN;
        build_ev_kernel<<<(m + 255)/256, 256>>>(encoded, true_value);
        int q = ROWS*384;
        build_attin_kernel<<<(q + 255)/256, 256>>>(encoded);
    }
    tcg(ev, DIN, wk, b_key, keys, KVROWS, HD, DIN, 0,
        (long long)DIN*HD, HD, (long long)KVROWS*HD, LL);
    tcg(ev, DIN, wv, b_val, vals, KVROWS, HD, DIN, 0,
        (long long)DIN*HD, HD, (long long)KVROWS*HD, LL);
    tcg(attin, 384, W_shift, b_shift, attv, ROWS, HD, 384, 0, 0, 0, 0, 1);
    for (int l = 0; l < LL; l++) {
        attn_kernel<<<dim3(BNB, HH), 256>>>(attv,
            keys + (long long)l*KVROWS*HD,
            vals + (long long)l*KVROWS*HD, attbuf);
        add_ln_kernel<<<ROWS, 256>>>(attv, attbuf, ln1_s + l*HD, ln1_b + l*HD);
        tcg(attv, HD, ff_w1 + (long long)l*HD*HD, ff_b1 + l*HD, f1, ROWS, HD, HD, 1, 0, 0, 0, 1);
        tcg(f1,   HD, ff_w2 + (long long)l*HD*HD, ff_b2 + l*HD, f2, ROWS, HD, HD, 0, 0, 0, 0, 1);
        add_ln_kernel<<<ROWS, 256>>>(attv, f2, ln2_s + l*HD, ln2_b + l*HD);
    }
    {
        int n = ROWS*VV;
        init_flow_kernel<<<(n + 255)/256, 256>>>(true_value);
        int n2 = ROWS*HD;
        copy_y_kernel<<<(n2 + 255)/256, 256>>>();
    }
    for (int blk = 0; blk < NB; blk++) {
        {
            int n = ROWS*VV;
            write_mu_kernel<<<(n + 255)/256, 256>>>(blk);
        }
        tcg(inp, CY, s_w_in + (long long)blk*CY*HD, s_b_in + blk*HD, h1, ROWS, HD, CY, 2, 0, 0, 0, 1);
        {
            float* bufs[5] = {h1, h2, h1, h2, h1};
            for (int i = 0; i < NHID; i++)
                tcg(bufs[i], HD, s_w_hid + (long long)(blk*NHID + i)*HD*HD,
                    s_b_hid + (long long)(blk*NHID + i)*HD, bufs[i+1], ROWS, HD, HD, 2, 0, 0, 0, 1);
            gemm_out3_kernel<<<(ROWS*32 + 255)/256, 256>>>(bufs[NHID],
                s_w_out + (long long)blk*HD*VV, s_b_out + blk*VV, snet);
        }
        tcg(inp, CY, t_w_in + (long long)blk*CY*HD, t_b_in + blk*HD, h1, ROWS, HD, CY, 1, 0, 0, 0, 1);
        {
            float* bufs[5] = {h1, h2, h1, h2, h1};
            for (int i = 0; i < NHID; i++)
                tcg(bufs[i], HD, t_w_hid + (long long)(blk*NHID + i)*HD*HD,
                    t_b_hid + (long long)(blk*NHID + i)*HD, bufs[i+1], ROWS, HD, HD, 1, 0, 0, 0, 1);
            gemm_out3_kernel<<<(ROWS*32 + 255)/256, 256>>>(bufs[NHID],
                t_w_out + (long long)blk*HD*VV, t_b_out + blk*VV, tnet);
        }
        {
            int n = ROWS*VV;
            coupling_kernel<<<(n + 255)/256, 256>>>(blk);
            bn_stats_kernel<<<T2*VV, 256>>>();
            bn_apply_kernel<<<(n + 255)/256, 256>>>(bn_lg, bn_be, blk);
        }
    }
    final_kernel<<<(BNB + 255)/256, 256>>>(out);
}

// round 4
// speedup vs baseline: 2.4616x; 1.2037x over previous
#include <cuda_runtime.h>
#include <mma.h>
#include <cstdint>
#include <math.h>

using namespace nvcuda;

// ---------------- problem constants ----------------
#define BNB   650
#define TT    48
#define T2    12
#define VV    3
#define CC    128
#define DIN   387
#define EVLD  388          // padded ev stride (16B-aligned rows)
#define HD    512
#define HH    8
#define DD    64
#define LL    4
#define NB    6
#define NHID  4
#define CY    515
#define INLD  516          // padded inp stride
#define ROWS  (BNB*T2)     // 7800
#define KVROWS (BNB*TT)    // 31200
#define LOG2PI 1.8378770664093453f

// ---------------- scratch ----------------
__device__ float g_ev[BNB*TT*EVLD];
__device__ float g_wk[LL*DIN*HD];
__device__ float g_wv[LL*DIN*HD];
__device__ float g_keys[LL*KVROWS*HD];
__device__ float g_vals[LL*KVROWS*HD];
__device__ float g_attin[ROWS*384];
__device__ float g_attv[ROWS*HD];
__device__ float g_attbuf[ROWS*HD];
__device__ float g_f1[ROWS*HD];
__device__ float g_f2[ROWS*HD];
__device__ float g_inp[ROWS*INLD];
__device__ float g_hA[2*ROWS*HD];     // [net][row][col]
__device__ float g_hB[2*ROWS*HD];
__device__ float g_snet[ROWS*VV];
__device__ float g_tnet[ROWS*VV];
__device__ float g_u[ROWS*VV];
__device__ float g_ld[ROWS*VV];
__device__ float g_stats[2*T2*VV];
// packed flow weights: [blk][net][...]
__device__ float g_win[NB*2*CY*HD];
__device__ float g_bin[NB*2*HD];
__device__ float g_whid[NB*NHID*2*HD*HD];
__device__ float g_bhid[NB*NHID*2*HD];

__device__ __forceinline__ float epi_act(float v, int act) {
    if (act == 1) return fmaxf(v, 0.f);
    if (act == 2) return tanhf(v);
    return v;
}

__device__ __forceinline__ void cpa16(uint32_t dst, const float* src, int sz) {
    asm volatile("cp.async.cg.shared.global [%0], [%1], 16, %2;"
                 :: "r"(dst), "l"(src), "r"(sz));
}
__device__ __forceinline__ void cpa_commit() {
    asm volatile("cp.async.commit_group;" ::: "memory");
}

// ---------------- wmma tf32 GEMM, cp.async double-buffered ----------------
// C[M,N] = act(A[M,K] @ B[K,N] + bias). 128x128 CTA tile, 8 warps of 32x64.
// Requires: lda%4==0, Kpad%4==0, N%128==0.
#define ALD 36
#define BLD 132
#define A_STG (128*ALD)               // 4608 floats (only [.,0:32) filled)
#define B_STG (32*BLD)                // 4224 floats
#define STG   (A_STG + B_STG)         // 8832 floats
#define WM_SMEM (2*STG*4)             // 70656 bytes; C staging (67584) overlays

__global__ __launch_bounds__(256) void wmma_gemm(
    const float* __restrict__ A, int lda, long long sA,
    const float* __restrict__ B, const float* __restrict__ bias,
    float* __restrict__ C,
    int M, int N, int Kpad, int Kreal, int act0, int act1,
    long long sB, long long sBias, long long sC)
{
    extern __shared__ float sm[];
    long long z = blockIdx.z;
    A    += z * sA;
    B    += z * sB;
    bias += z * sBias;
    C    += z * sC;
    int act = (z == 0) ? act0 : act1;

    int bm = blockIdx.x * 128, bn = blockIdx.y * 128;
    int tid = threadIdx.x, wid = tid >> 5;
    int warp_m = wid >> 1, warp_n = wid & 1;

    wmma::fragment<wmma::accumulator, 16, 16, 8, float> acc[2][4];
    #pragma unroll
    for (int i = 0; i < 2; i++)
        #pragma unroll
        for (int j = 0; j < 4; j++) wmma::fill_fragment(acc[i][j], 0.f);

    int nch = (Kpad + 31) >> 5;

    auto load_stage = [&](int s, int c) {
        uint32_t base = (uint32_t)__cvta_generic_to_shared(sm + s * STG);
        uint32_t bBase = base + A_STG * 4;
        int k0 = c << 5;
        #pragma unroll
        for (int it = 0; it < 4; it++) {
            int q = it * 256 + tid;
            int r = q >> 3, kk = (q & 7) << 2;
            int gm = bm + r, gk = k0 + kk;
            int ok = (gm < M && gk < Kpad);
            int cgm = ok ? gm : 0, cgk = ok ? gk : 0;
            cpa16(base + (uint32_t)(r * ALD + kk) * 4,
                  A + (long long)cgm * lda + cgk, ok ? 16 : 0);
        }
        #pragma unroll
        for (int it = 0; it < 4; it++) {
            int q = it * 256 + tid;
            int kk = q >> 5, n = (q & 31) << 2;
            int gk = k0 + kk;
            int ok = (gk < Kreal);
            int cgk = ok ? gk : 0;
            cpa16(bBase + (uint32_t)(kk * BLD + n) * 4,
                  B + (long long)cgk * N + bn + n, ok ? 16 : 0);
        }
    };

    load_stage(0, 0);
    cpa_commit();

    for (int c = 0; c < nch; c++) {
        bool more = (c + 1 < nch);
        if (more) { load_stage((c + 1) & 1, c + 1); cpa_commit(); }
        if (more) asm volatile("cp.async.wait_group 1;" ::: "memory");
        else      asm volatile("cp.async.wait_group 0;" ::: "memory");
        __syncthreads();
        float* As = sm + (c & 1) * STG;
        float* Bs = As + A_STG;
        #pragma unroll
        for (int ks = 0; ks < 4; ks++) {
            int k0 = ks * 8;
            wmma::fragment<wmma::matrix_a, 16, 16, 8, wmma::precision::tf32, wmma::row_major> af[2];
            wmma::fragment<wmma::matrix_b, 16, 16, 8, wmma::precision::tf32, wmma::row_major> bf[4];
            #pragma unroll
            for (int i = 0; i < 2; i++) {
                wmma::load_matrix_sync(af[i], As + (warp_m*32 + i*16) * ALD + k0, ALD);
                #pragma unroll
                for (int t = 0; t < af[i].num_elements; t++)
                    af[i].x[t] = wmma::__float_to_tf32(af[i].x[t]);
            }
            #pragma unroll
            for (int j = 0; j < 4; j++) {
                wmma::load_matrix_sync(bf[j], Bs + k0 * BLD + warp_n*64 + j*16, BLD);
                #pragma unroll
                for (int t = 0; t < bf[j].num_elements; t++)
                    bf[j].x[t] = wmma::__float_to_tf32(bf[j].x[t]);
            }
            #pragma unroll
            for (int i = 0; i < 2; i++)
                #pragma unroll
                for (int j = 0; j < 4; j++)
                    wmma::mma_sync(acc[i][j], af[i], bf[j], acc[i][j]);
        }
        __syncthreads();
    }

    float* Cs = sm;
    #pragma unroll
    for (int i = 0; i < 2; i++)
        #pragma unroll
        for (int j = 0; j < 4; j++)
            wmma::store_matrix_sync(Cs + (warp_m*32 + i*16) * BLD + warp_n*64 + j*16,
                                    acc[i][j], BLD, wmma::mem_row_major);
    __syncthreads();

    #pragma unroll
    for (int it = 0; it < 16; it++) {
        int idx = it * 256 + tid;
        int r = idx >> 5, c4 = (idx & 31) * 4;
        int gm = bm + r;
        if (gm >= M) continue;
        int gc = bn + c4;
        float4 v;
        v.x = epi_act(Cs[r * BLD + c4 + 0] + bias[gc + 0], act);
        v.y = epi_act(Cs[r * BLD + c4 + 1] + bias[gc + 1], act);
        v.z = epi_act(Cs[r * BLD + c4 + 2] + bias[gc + 2], act);
        v.w = epi_act(Cs[r * BLD + c4 + 3] + bias[gc + 3], act);
        *(float4*)(C + (long long)gm * N + gc) = v;
    }
}

// ---------------- pack kernels (flow weights -> contiguous [blk][net]) ------
__global__ void pack_win_kernel(const float* __restrict__ s, const float* __restrict__ t)
{
    int idx = blockIdx.x * blockDim.x + threadIdx.x;
    const int per = CY*HD;
    if (idx >= NB*2*per) return;
    int blk = idx / (2*per);
    int r = idx - blk*2*per;
    int net = r / per, off = r - net*per;
    g_win[idx] = net ? t[(long long)blk*per + off] : s[(long long)blk*per + off];
}
__global__ void pack_bin_kernel(const float* __restrict__ s, const float* __restrict__ t)
{
    int idx = blockIdx.x * blockDim.x + threadIdx.x;
    if (idx >= NB*2*HD) return;
    int blk = idx / (2*HD);
    int r = idx - blk*2*HD;
    int net = r / HD, off = r - net*HD;
    g_bin[idx] = net ? t[blk*HD + off] : s[blk*HD + off];
}
__global__ void pack_whid_kernel(const float* __restrict__ s, const float* __restrict__ t)
{
    long long idx = (long long)blockIdx.x * blockDim.x + threadIdx.x;
    const long long per = HD*HD;
    if (idx >= (long long)NB*NHID*2*per) return;
    long long u = idx / (2*per);                 // blk*NHID + i
    long long r = idx - u*2*per;
    int net = (int)(r / per);
    long long off = r - (long long)net*per;
    g_whid[idx] = net ? t[u*per + off] : s[u*per + off];
}
__global__ void pack_bhid_kernel(const float* __restrict__ s, const float* __restrict__ t)
{
    int idx = blockIdx.x * blockDim.x + threadIdx.x;
    if (idx >= NB*NHID*2*HD) return;
    int u = idx / (2*HD);
    int r = idx - u*2*HD;
    int net = r / HD, off = r - net*HD;
    g_bhid[idx] = net ? t[u*HD + off] : s[u*HD + off];
}

// ---------------- small kernels ----------------
__global__ void transpose_w_kernel(const float* __restrict__ W, float* __restrict__ out)
{
    int idx = blockIdx.x * blockDim.x + threadIdx.x;
    if (idx >= LL*DIN*HD) return;
    int l = idx / (DIN*HD);
    int rem = idx - l * (DIN*HD);
    int e = rem / HD;
    int n = rem - e * HD;
    int h = n >> 6, d = n & 63;
    out[idx] = W[(((long long)l*HH + h)*DIN + e)*DD + d];
}

__global__ void build_ev_kernel(const float* __restrict__ encoded,
                                const float* __restrict__ tv)
{
    int idx = blockIdx.x * blockDim.x + threadIdx.x;
    if (idx >= BNB*TT*EVLD) return;
    int bn = idx / (TT*EVLD);
    int rem = idx - bn * (TT*EVLD);
    int t = rem / EVLD;
    int e = rem - t * EVLD;
    float val = 0.f;
    if (e < DIN) {
        int v = e / (CC+1);
        int j = e - v * (CC+1);
        if (j < CC) val = encoded[(((long long)bn*VV + v)*TT + t)*CC + j];
        else        val = tv[((long long)bn*VV + v)*TT + t];
    }
    g_ev[idx] = val;
}

__global__ void build_attin_kernel(const float* __restrict__ encoded)
{
    int idx = blockIdx.x * blockDim.x + threadIdx.x;
    if (idx >= ROWS*384) return;
    int row = idx / 384;
    int col = idx - row*384;
    int bn = row / T2, t2 = row - bn*T2;
    int v = col >> 7, j = col & 127;
    g_attin[idx] = encoded[(((long long)bn*VV + v)*TT + (TT - T2 + t2))*CC + j];
}

__global__ void attn_kernel(const float* __restrict__ attv,
                            const float* __restrict__ keys_l,
                            const float* __restrict__ vals_l,
                            float* __restrict__ attbuf)
{
    int bn = blockIdx.x, h = blockIdx.y;
    __shared__ float Qs[T2*DD];
    __shared__ float Ks[TT*DD];
    __shared__ float Vs[TT*DD];
    __shared__ float Ss[T2*TT];
    int tid = threadIdx.x;
    const float* kb = keys_l + (long long)bn*TT*HD + h*DD;
    const float* vb = vals_l + (long long)bn*TT*HD + h*DD;
    for (int i = tid; i < TT*DD; i += 256) {
        int t = i >> 6, d = i & 63;
        Ks[i] = kb[(long long)t*HD + d];
        Vs[i] = vb[(long long)t*HD + d];
    }
    for (int i = tid; i < T2*DD; i += 256) {
        int v = i >> 6, d = i & 63;
        Qs[i] = attv[((long long)bn*T2 + v)*HD + h*DD + d];
    }
    __syncthreads();
    const float scale = 0.125f;
    for (int i = tid; i < T2*TT; i += 256) {
        int v = i / TT, w = i - v*TT;
        float s;
        if (w >= (TT - T2) + v) s = -INFINITY;
        else {
            float a = 0.f;
            #pragma unroll
            for (int d = 0; d < DD; d++) a += Qs[v*DD+d] * Ks[w*DD+d];
            s = a * scale;
        }
        Ss[i] = s;
    }
    __syncthreads();
    if (tid < T2) {
        int v = tid;
        float m = -INFINITY;
        for (int w = 0; w < TT; w++) m = fmaxf(m, Ss[v*TT+w]);
        float sum = 0.f;
        for (int w = 0; w < TT; w++) {
            float e = expf(Ss[v*TT+w] - m);
            Ss[v*TT+w] = e; sum += e;
        }
        float inv = 1.f / sum;
        for (int w = 0; w < TT; w++) Ss[v*TT+w] *= inv;
    }
    __syncthreads();
    for (int i = tid; i < T2*DD; i += 256) {
        int v = i >> 6, d = i & 63;
        float a = 0.f;
        #pragma unroll
        for (int w = 0; w < TT; w++) a += Ss[v*TT+w] * Vs[w*DD+d];
        attbuf[((long long)bn*T2 + v)*HD + h*DD + d] = a;
    }
}

__global__ void add_ln_kernel(float* __restrict__ x, const float* __restrict__ r,
                              const float* __restrict__ g, const float* __restrict__ b)
{
    int row = blockIdx.x;
    int tid = threadIdx.x;
    __shared__ float red[256];
    long long base = (long long)row * HD;
    float v0 = x[base + tid] + r[base + tid];
    float v1 = x[base + tid + 256] + r[base + tid + 256];
    red[tid] = v0 + v1;
    __syncthreads();
    for (int s = 128; s > 0; s >>= 1) { if (tid < s) red[tid] += red[tid+s]; __syncthreads(); }
    float mean = red[0] * (1.f/512.f);
    __syncthreads();
    float d0 = v0 - mean, d1 = v1 - mean;
    red[tid] = d0*d0 + d1*d1;
    __syncthreads();
    for (int s = 128; s > 0; s >>= 1) { if (tid < s) red[tid] += red[tid+s]; __syncthreads(); }
    float rstd = rsqrtf(red[0] * (1.f/512.f) + 1e-5f);
    x[base + tid]       = d0 * rstd * g[tid]       + b[tid];
    x[base + tid + 256] = d1 * rstd * g[tid + 256] + b[tid + 256];
}

__global__ void init_flow_kernel(const float* __restrict__ tv)
{
    int idx = blockIdx.x * blockDim.x + threadIdx.x;
    if (idx >= ROWS*VV) return;
    int bn = idx / (T2*VV);
    int rem = idx - bn * (T2*VV);
    int t2 = rem / VV, v = rem - t2*VV;
    g_u[idx] = tv[((long long)bn*VV + v)*TT + (TT - T2 + t2)];
    g_ld[idx] = 0.f;
}

__global__ void copy_y_kernel()
{
    int idx = blockIdx.x * blockDim.x + threadIdx.x;
    if (idx >= ROWS*INLD) return;
    int row = idx / INLD, col = idx - row*INLD;
    if (col < HD)        g_inp[idx] = g_attv[(long long)row*HD + col];
    else if (col == 515) g_inp[idx] = 0.f;
    // cols 512..514 written by write_mu each block
}

__global__ void write_mu_kernel(int blk)
{
    int idx = blockIdx.x * blockDim.x + threadIdx.x;
    if (idx >= ROWS*VV) return;
    int row = idx / VV, v = idx - row*VV;
    float mask = (float)((v + blk) & 1);
    g_inp[(long long)row * INLD + HD + v] = g_u[idx] * mask;
}

// batched out3: z=blockIdx.y selects (A half, W, bias, out)
__global__ void gemm_out3_kernel(const float* __restrict__ Acat,
                                 const float* __restrict__ Ws, const float* __restrict__ bs,
                                 const float* __restrict__ Wt, const float* __restrict__ bt,
                                 float* __restrict__ snet, float* __restrict__ tnet)
{
    int z = blockIdx.y;
    const float* A = Acat + (long long)z * ROWS * HD;
    const float* W = z ? Wt : Ws;
    const float* bias = z ? bt : bs;
    float* out = z ? tnet : snet;
    int gw = (blockIdx.x * blockDim.x + threadIdx.x) >> 5;
    int lane = threadIdx.x & 31;
    if (gw >= ROWS) return;
    const float* a = A + (long long)gw * HD;
    float s0 = 0.f, s1 = 0.f, s2 = 0.f;
    for (int k = lane; k < HD; k += 32) {
        float av = a[k];
        s0 += av * W[k*3 + 0];
        s1 += av * W[k*3 + 1];
        s2 += av * W[k*3 + 2];
    }
    #pragma unroll
    for (int off = 16; off > 0; off >>= 1) {
        s0 += __shfl_down_sync(0xffffffffu, s0, off);
        s1 += __shfl_down_sync(0xffffffffu, s1, off);
        s2 += __shfl_down_sync(0xffffffffu, s2, off);
    }
    if (lane == 0) {
        out[gw*3 + 0] = s0 + bias[0];
        out[gw*3 + 1] = s1 + bias[1];
        out[gw*3 + 2] = s2 + bias[2];
    }
}

__global__ void coupling_kernel(int blk)
{
    int idx = blockIdx.x * blockDim.x + threadIdx.x;
    if (idx >= ROWS*VV) return;
    int v = idx % VV;
    if (((v + blk) & 1) == 0) {
        float s = g_snet[idx];
        g_u[idx] = (g_u[idx] - g_tnet[idx]) * expf(-s);
        g_ld[idx] -= s;
    }
}

__global__ void bn_stats_kernel()
{
    int col = blockIdx.x;
    int tid = threadIdx.x;
    __shared__ float rs[256], rq[256];
    float s = 0.f, q = 0.f;
    for (int bn = tid; bn < BNB; bn += 256) {
        float v = g_u[bn*(T2*VV) + col];
        s += v; q += v*v;
    }
    rs[tid] = s; rq[tid] = q;
    __syncthreads();
    for (int st = 128; st > 0; st >>= 1) {
        if (tid < st) { rs[tid] += rs[tid+st]; rq[tid] += rq[tid+st]; }
        __syncthreads();
    }
    if (tid == 0) {
        float m = rs[0] / (float)BNB;
        float var = rq[0] / (float)BNB - m*m;
        g_stats[col] = m;
        g_stats[T2*VV + col] = fmaxf(var, 0.f);
    }
}

__global__ void bn_apply_kernel(const float* __restrict__ lg,
                                const float* __restrict__ beta, int blk)
{
    int idx = blockIdx.x * blockDim.x + threadIdx.x;
    if (idx >= ROWS*VV) return;
    int col = idx % (T2*VV);
    int v = idx % VV;
    float m = g_stats[col];
    float var = g_stats[T2*VV + col];
    float gg = lg[blk*VV + v];
    float be = beta[blk*VV + v];
    float r = rsqrtf(var + 1e-5f);
    g_u[idx] = expf(gg) * (g_u[idx] - m) * r + be;
    g_ld[idx] += gg - 0.5f * logf(var + 1e-5f);
}

__global__ void final_kernel(float* __restrict__ out)
{
    int bn = blockIdx.x * blockDim.x + threadIdx.x;
    if (bn >= BNB) return;
    float acc = 0.f;
    #pragma unroll
    for (int i = 0; i < T2*VV; i++) {
        float u = g_u[bn*(T2*VV) + i];
        acc += 0.5f*u*u + 0.5f*LOG2PI - g_ld[bn*(T2*VV) + i];
    }
    out[bn] = acc;
}

// ---------------- host launcher ----------------
static inline void tcg(const float* A, int lda, long long sA,
                       const float* B, const float* bias, float* C,
                       int M, int N, int Kpad, int Kreal, int act0, int act1,
                       long long sB, long long sBias, long long sC, int Z)
{
    dim3 grid((M + 127)/128, N/128, Z);
    wmma_gemm<<<grid, 256, WM_SMEM>>>(A, lda, sA, B, bias, C,
                                      M, N, Kpad, Kreal, act0, act1, sB, sBias, sC);
}

extern "C" void kernel_launch(void* const* d_in, const int* in_sizes, int n_in,
                              void* d_out, int out_size)
{
    const float* encoded    = (const float*)d_in[0];
    const float* true_value = (const float*)d_in[1];
    const float* W_shift    = (const float*)d_in[2];
    const float* b_shift    = (const float*)d_in[3];
    const float* W_key      = (const float*)d_in[4];
    const float* b_key      = (const float*)d_in[5];
    const float* W_val      = (const float*)d_in[6];
    const float* b_val      = (const float*)d_in[7];
    const float* ln1_s      = (const float*)d_in[8];
    const float* ln1_b      = (const float*)d_in[9];
    const float* ff_w1      = (const float*)d_in[10];
    const float* ff_b1      = (const float*)d_in[11];
    const float* ff_w2      = (const float*)d_in[12];
    const float* ff_b2      = (const float*)d_in[13];
    const float* ln2_s      = (const float*)d_in[14];
    const float* ln2_b      = (const float*)d_in[15];
    const float* s_w_in     = (const float*)d_in[16];
    const float* s_b_in     = (const float*)d_in[17];
    const float* s_w_hid    = (const float*)d_in[18];
    const float* s_b_hid    = (const float*)d_in[19];
    const float* s_w_out    = (const float*)d_in[20];
    const float* s_b_out    = (const float*)d_in[21];
    const float* t_w_in     = (const float*)d_in[22];
    const float* t_b_in     = (const float*)d_in[23];
    const float* t_w_hid    = (const float*)d_in[24];
    const float* t_b_hid    = (const float*)d_in[25];
    const float* t_w_out    = (const float*)d_in[26];
    const float* t_b_out    = (const float*)d_in[27];
    const float* bn_lg      = (const float*)d_in[28];
    const float* bn_be      = (const float*)d_in[29];
    float* out = (float*)d_out;

    cudaFuncSetAttribute(wmma_gemm, cudaFuncAttributeMaxDynamicSharedMemorySize, WM_SMEM);

    float *ev, *wk, *wv, *keys, *vals, *attin, *attv, *attbuf, *f1, *f2, *inp;
    float *hA, *hB, *snet, *tnet, *win, *bin, *whid, *bhid;
    cudaGetSymbolAddress((void**)&ev,     g_ev);
    cudaGetSymbolAddress((void**)&wk,     g_wk);
    cudaGetSymbolAddress((void**)&wv,     g_wv);
    cudaGetSymbolAddress((void**)&keys,   g_keys);
    cudaGetSymbolAddress((void**)&vals,   g_vals);
    cudaGetSymbolAddress((void**)&attin,  g_attin);
    cudaGetSymbolAddress((void**)&attv,   g_attv);
    cudaGetSymbolAddress((void**)&attbuf, g_attbuf);
    cudaGetSymbolAddress((void**)&f1,     g_f1);
    cudaGetSymbolAddress((void**)&f2,     g_f2);
    cudaGetSymbolAddress((void**)&inp,    g_inp);
    cudaGetSymbolAddress((void**)&hA,     g_hA);
    cudaGetSymbolAddress((void**)&hB,     g_hB);
    cudaGetSymbolAddress((void**)&snet,   g_snet);
    cudaGetSymbolAddress((void**)&tnet,   g_tnet);
    cudaGetSymbolAddress((void**)&win,    g_win);
    cudaGetSymbolAddress((void**)&bin,    g_bin);
    cudaGetSymbolAddress((void**)&whid,   g_whid);
    cudaGetSymbolAddress((void**)&bhid,   g_bhid);

    // builds + packs
    {
        int n = LL*DIN*HD;
        transpose_w_kernel<<<(n + 255)/256, 256>>>(W_key, wk);
        transpose_w_kernel<<<(n + 255)/256, 256>>>(W_val, wv);
        int m = BNB*TT*EVLD;
        build_ev_kernel<<<(m + 255)/256, 256>>>(encoded, true_value);
        int q = ROWS*384;
        build_attin_kernel<<<(q + 255)/256, 256>>>(encoded);
        int p1 = NB*2*CY*HD;
        pack_win_kernel<<<(p1 + 255)/256, 256>>>(s_w_in, t_w_in);
        int p2 = NB*2*HD;
        pack_bin_kernel<<<(p2 + 255)/256, 256>>>(s_b_in, t_b_in);
        long long p3 = (long long)NB*NHID*2*HD*HD;
        pack_whid_kernel<<<(int)((p3 + 255)/256), 256>>>(s_w_hid, t_w_hid);
        int p4 = NB*NHID*2*HD;
        pack_bhid_kernel<<<(p4 + 255)/256, 256>>>(s_b_hid, t_b_hid);
    }
    // K/V projections: z=4 layers
    tcg(ev, EVLD, 0, wk, b_key, keys, KVROWS, HD, EVLD, DIN, 0, 0,
        (long long)DIN*HD, HD, (long long)KVROWS*HD, LL);
    tcg(ev, EVLD, 0, wv, b_val, vals, KVROWS, HD, EVLD, DIN, 0, 0,
        (long long)DIN*HD, HD, (long long)KVROWS*HD, LL);
    // query shift
    tcg(attin, 384, 0, W_shift, b_shift, attv, ROWS, HD, 384, 384, 0, 0, 0, 0, 0, 1);
    // transformer layers
    for (int l = 0; l < LL; l++) {
        attn_kernel<<<dim3(BNB, HH), 256>>>(attv,
            keys + (long long)l*KVROWS*HD,
            vals + (long long)l*KVROWS*HD, attbuf);
        add_ln_kernel<<<ROWS, 256>>>(attv, attbuf, ln1_s + l*HD, ln1_b + l*HD);
        tcg(attv, HD, 0, ff_w1 + (long long)l*HD*HD, ff_b1 + l*HD, f1,
            ROWS, HD, HD, HD, 1, 1, 0, 0, 0, 1);
        tcg(f1, HD, 0, ff_w2 + (long long)l*HD*HD, ff_b2 + l*HD, f2,
            ROWS, HD, HD, HD, 0, 0, 0, 0, 0, 1);
        add_ln_kernel<<<ROWS, 256>>>(attv, f2, ln2_s + l*HD, ln2_b + l*HD);
    }
    // flow init
    {
        int n = ROWS*VV;
        init_flow_kernel<<<(n + 255)/256, 256>>>(true_value);
        int n2 = ROWS*INLD;
        copy_y_kernel<<<(n2 + 255)/256, 256>>>();
    }
    const long long perW = (long long)CY*HD;
    const long long perH = (long long)HD*HD;
    const long long sCh  = (long long)ROWS*HD;
    for (int blk = 0; blk < NB; blk++) {
        {
            int n = ROWS*VV;
            write_mu_kernel<<<(n + 255)/256, 256>>>(blk);
        }
        // input layer (z=2: s=tanh, t=relu), A shared (sA=0)
        tcg(inp, INLD, 0, win + (long long)blk*2*perW, bin + (long long)blk*2*HD, hA,
            ROWS, HD, INLD, CY, 2, 1, perW, HD, sCh, 2);
        // hidden layers (z=2), ping-pong hA/hB
        float* bufs[5] = {hA, hB, hA, hB, hA};
        for (int i = 0; i < NHID; i++) {
            long long wo = ((long long)(blk*NHID + i))*2;
            tcg(bufs[i], HD, sCh, whid + wo*perH, bhid + wo*HD, bufs[i+1],
                ROWS, HD, HD, HD, 2, 1, perH, HD, sCh, 2);
        }
        // output layer (z=2 in grid.y)
        gemm_out3_kernel<<<dim3((ROWS*32 + 255)/256, 2), 256>>>(bufs[NHID],
            s_w_out + (long long)blk*HD*VV, s_b_out + blk*VV,
            t_w_out + (long long)blk*HD*VV, t_b_out + blk*VV, snet, tnet);
        {
            int n = ROWS*VV;
            coupling_kernel<<<(n + 255)/256, 256>>>(blk);
            bn_stats_kernel<<<T2*VV, 256>>>();
            bn_apply_kernel<<<(n + 255)/256, 256>>>(bn_lg, bn_be, blk);
        }
    }
    final_kernel<<<(BNB + 255)/256, 256>>>(out);
}

// round 5
// speedup vs baseline: 2.9376x; 1.1934x over previous
#include <cuda_runtime.h>
#include <mma.h>
#include <cstdint>
#include <math.h>

using namespace nvcuda;

// ---------------- problem constants ----------------
#define BNB   650
#define TT    48
#define T2    12
#define VV    3
#define CC    128
#define DIN   387
#define EVLD  388
#define HD    512
#define HH    8
#define DD    64
#define LL    4
#define NB    6
#define NHID  4
#define CY    515
#define INLD  516
#define ROWS  (BNB*T2)     // 7800
#define KVROWS (BNB*TT)    // 31200
#define LOG2PI 1.8378770664093453f

// ---------------- scratch ----------------
__device__ float g_ev[BNB*TT*EVLD];
__device__ float g_wk[LL*DIN*HD];
__device__ float g_wv[LL*DIN*HD];
__device__ float g_keys[LL*KVROWS*HD];
__device__ float g_vals[LL*KVROWS*HD];
__device__ float g_attin[ROWS*384];
__device__ float g_attv[ROWS*HD];
__device__ float g_attbuf[ROWS*HD];
__device__ float g_f1[ROWS*HD];
__device__ float g_f2[ROWS*HD];
__device__ float g_inp[ROWS*INLD];
__device__ float g_hA[2*ROWS*HD];
__device__ float g_hB[2*ROWS*HD];
__device__ float g_u[ROWS*VV];
__device__ float g_ld[ROWS*VV];
__device__ float g_stats[2*T2*VV];
__device__ float g_win[NB*2*CY*HD];
__device__ float g_bin[NB*2*HD];
__device__ float g_whid[NB*NHID*2*HD*HD];
__device__ float g_bhid[NB*NHID*2*HD];

__device__ __forceinline__ float epi_act(float v, int act) {
    if (act == 1) return fmaxf(v, 0.f);
    if (act == 2) return tanhf(v);
    return v;
}

__device__ __forceinline__ void cpa16(uint32_t dst, const float* src, int sz) {
    asm volatile("cp.async.cg.shared.global [%0], [%1], 16, %2;"
                 :: "r"(dst), "l"(src), "r"(sz));
}
__device__ __forceinline__ void cpa_commit() {
    asm volatile("cp.async.commit_group;" ::: "memory");
}

// ---------------- wmma tf32 GEMM, 3-stage cp.async, 1 sync/chunk ----------
#define ALD 36
#define BLD 132
#define A_STG (128*ALD)
#define B_STG (32*BLD)
#define STG   (A_STG + B_STG)          // 8832 floats / stage
#define NSTAGE 3
#define WM_SMEM (NSTAGE*STG*4)         // 105984 B; C staging (67584 B) overlays

__global__ __launch_bounds__(256, 2) void wmma_gemm(
    const float* __restrict__ A, int lda, long long sA,
    const float* __restrict__ B, const float* __restrict__ bias,
    float* __restrict__ C,
    int M, int N, int Kpad, int Kreal, int act0, int act1,
    long long sB, long long sBias, long long sC)
{
    extern __shared__ float sm[];
    long long z = blockIdx.z;
    A    += z * sA;
    B    += z * sB;
    bias += z * sBias;
    C    += z * sC;
    int act = (z == 0) ? act0 : act1;

    int bm = blockIdx.x * 128, bn = blockIdx.y * 128;
    int tid = threadIdx.x, wid = tid >> 5;
    int warp_m = wid >> 1, warp_n = wid & 1;

    wmma::fragment<wmma::accumulator, 16, 16, 8, float> acc[2][4];
    #pragma unroll
    for (int i = 0; i < 2; i++)
        #pragma unroll
        for (int j = 0; j < 4; j++) wmma::fill_fragment(acc[i][j], 0.f);

    int nch = (Kpad + 31) >> 5;

    auto load_stage = [&](int s, int c) {
        uint32_t base = (uint32_t)__cvta_generic_to_shared(sm + s * STG);
        uint32_t bBase = base + A_STG * 4;
        int k0 = c << 5;
        #pragma unroll
        for (int it = 0; it < 4; it++) {
            int q = it * 256 + tid;
            int r = q >> 3, kk = (q & 7) << 2;
            int gm = bm + r, gk = k0 + kk;
            int ok = (gm < M && gk < Kpad);
            int cgm = ok ? gm : 0, cgk = ok ? gk : 0;
            cpa16(base + (uint32_t)(r * ALD + kk) * 4,
                  A + (long long)cgm * lda + cgk, ok ? 16 : 0);
        }
        #pragma unroll
        for (int it = 0; it < 4; it++) {
            int q = it * 256 + tid;
            int kk = q >> 5, n = (q & 31) << 2;
            int gk = k0 + kk;
            int ok = (gk < Kreal);
            int cgk = ok ? gk : 0;
            cpa16(bBase + (uint32_t)(kk * BLD + n) * 4,
                  B + (long long)cgk * N + bn + n, ok ? 16 : 0);
        }
    };

    load_stage(0, 0);
    cpa_commit();
    if (nch > 1) { load_stage(1, 1); cpa_commit(); }

    for (int c = 0; c < nch; c++) {
        if (c + 1 < nch) asm volatile("cp.async.wait_group 1;" ::: "memory");
        else             asm volatile("cp.async.wait_group 0;" ::: "memory");
        __syncthreads();
        if (c + 2 < nch) { load_stage((c + 2) % NSTAGE, c + 2); cpa_commit(); }

        float* As = sm + (c % NSTAGE) * STG;
        float* Bs = As + A_STG;
        #pragma unroll
        for (int ks = 0; ks < 4; ks++) {
            int k0 = ks * 8;
            wmma::fragment<wmma::matrix_a, 16, 16, 8, wmma::precision::tf32, wmma::row_major> af[2];
            wmma::fragment<wmma::matrix_b, 16, 16, 8, wmma::precision::tf32, wmma::row_major> bf[4];
            #pragma unroll
            for (int i = 0; i < 2; i++)
                wmma::load_matrix_sync(af[i], As + (warp_m*32 + i*16) * ALD + k0, ALD);
            #pragma unroll
            for (int j = 0; j < 4; j++)
                wmma::load_matrix_sync(bf[j], Bs + k0 * BLD + warp_n*64 + j*16, BLD);
            // NOTE: no __float_to_tf32 — HMMA.TF32 truncates fp32 operands in HW.
            #pragma unroll
            for (int i = 0; i < 2; i++)
                #pragma unroll
                for (int j = 0; j < 4; j++)
                    wmma::mma_sync(acc[i][j], af[i], bf[j], acc[i][j]);
        }
    }
    __syncthreads();

    float* Cs = sm;
    #pragma unroll
    for (int i = 0; i < 2; i++)
        #pragma unroll
        for (int j = 0; j < 4; j++)
            wmma::store_matrix_sync(Cs + (warp_m*32 + i*16) * BLD + warp_n*64 + j*16,
                                    acc[i][j], BLD, wmma::mem_row_major);
    __syncthreads();

    #pragma unroll
    for (int it = 0; it < 16; it++) {
        int idx = it * 256 + tid;
        int r = idx >> 5, c4 = (idx & 31) * 4;
        int gm = bm + r;
        if (gm >= M) continue;
        int gc = bn + c4;
        float4 v;
        v.x = epi_act(Cs[r * BLD + c4 + 0] + bias[gc + 0], act);
        v.y = epi_act(Cs[r * BLD + c4 + 1] + bias[gc + 1], act);
        v.z = epi_act(Cs[r * BLD + c4 + 2] + bias[gc + 2], act);
        v.w = epi_act(Cs[r * BLD + c4 + 3] + bias[gc + 3], act);
        *(float4*)(C + (long long)gm * N + gc) = v;
    }
}

// ---------------- pack kernels ----------------
__global__ void pack_win_kernel(const float* __restrict__ s, const float* __restrict__ t)
{
    int idx = blockIdx.x * blockDim.x + threadIdx.x;
    const int per = CY*HD;
    if (idx >= NB*2*per) return;
    int blk = idx / (2*per);
    int r = idx - blk*2*per;
    int net = r / per, off = r - net*per;
    g_win[idx] = net ? t[(long long)blk*per + off] : s[(long long)blk*per + off];
}
__global__ void pack_bin_kernel(const float* __restrict__ s, const float* __restrict__ t)
{
    int idx = blockIdx.x * blockDim.x + threadIdx.x;
    if (idx >= NB*2*HD) return;
    int blk = idx / (2*HD);
    int r = idx - blk*2*HD;
    int net = r / HD, off = r - net*HD;
    g_bin[idx] = net ? t[blk*HD + off] : s[blk*HD + off];
}
__global__ void pack_whid_kernel(const float* __restrict__ s, const float* __restrict__ t)
{
    long long idx = (long long)blockIdx.x * blockDim.x + threadIdx.x;
    const long long per = HD*HD;
    if (idx >= (long long)NB*NHID*2*per) return;
    long long u = idx / (2*per);
    long long r = idx - u*2*per;
    int net = (int)(r / per);
    long long off = r - (long long)net*per;
    g_whid[idx] = net ? t[u*per + off] : s[u*per + off];
}
__global__ void pack_bhid_kernel(const float* __restrict__ s, const float* __restrict__ t)
{
    int idx = blockIdx.x * blockDim.x + threadIdx.x;
    if (idx >= NB*NHID*2*HD) return;
    int u = idx / (2*HD);
    int r = idx - u*2*HD;
    int net = r / HD, off = r - net*HD;
    g_bhid[idx] = net ? t[u*HD + off] : s[u*HD + off];
}

// ---------------- small kernels ----------------
__global__ void transpose_w_kernel(const float* __restrict__ W, float* __restrict__ out)
{
    int idx = blockIdx.x * blockDim.x + threadIdx.x;
    if (idx >= LL*DIN*HD) return;
    int l = idx / (DIN*HD);
    int rem = idx - l * (DIN*HD);
    int e = rem / HD;
    int n = rem - e * HD;
    int h = n >> 6, d = n & 63;
    out[idx] = W[(((long long)l*HH + h)*DIN + e)*DD + d];
}

__global__ void build_ev_kernel(const float* __restrict__ encoded,
                                const float* __restrict__ tv)
{
    int idx = blockIdx.x * blockDim.x + threadIdx.x;
    if (idx >= BNB*TT*EVLD) return;
    int bn = idx / (TT*EVLD);
    int rem = idx - bn * (TT*EVLD);
    int t = rem / EVLD;
    int e = rem - t * EVLD;
    float val = 0.f;
    if (e < DIN) {
        int v = e / (CC+1);
        int j = e - v * (CC+1);
        if (j < CC) val = encoded[(((long long)bn*VV + v)*TT + t)*CC + j];
        else        val = tv[((long long)bn*VV + v)*TT + t];
    }
    g_ev[idx] = val;
}

__global__ void build_attin_kernel(const float* __restrict__ encoded)
{
    int idx = blockIdx.x * blockDim.x + threadIdx.x;
    if (idx >= ROWS*384) return;
    int row = idx / 384;
    int col = idx - row*384;
    int bn = row / T2, t2 = row - bn*T2;
    int v = col >> 7, j = col & 127;
    g_attin[idx] = encoded[(((long long)bn*VV + v)*TT + (TT - T2 + t2))*CC + j];
}

__global__ void attn_kernel(const float* __restrict__ attv,
                            const float* __restrict__ keys_l,
                            const float* __restrict__ vals_l,
                            float* __restrict__ attbuf)
{
    int bn = blockIdx.x, h = blockIdx.y;
    __shared__ float Qs[T2*DD];
    __shared__ float Ks[TT*DD];
    __shared__ float Vs[TT*DD];
    __shared__ float Ss[T2*TT];
    int tid = threadIdx.x;
    const float* kb = keys_l + (long long)bn*TT*HD + h*DD;
    const float* vb = vals_l + (long long)bn*TT*HD + h*DD;
    for (int i = tid; i < TT*DD; i += 256) {
        int t = i >> 6, d = i & 63;
        Ks[i] = kb[(long long)t*HD + d];
        Vs[i] = vb[(long long)t*HD + d];
    }
    for (int i = tid; i < T2*DD; i += 256) {
        int v = i >> 6, d = i & 63;
        Qs[i] = attv[((long long)bn*T2 + v)*HD + h*DD + d];
    }
    __syncthreads();
    const float scale = 0.125f;
    for (int i = tid; i < T2*TT; i += 256) {
        int v = i / TT, w = i - v*TT;
        float s;
        if (w >= (TT - T2) + v) s = -INFINITY;
        else {
            float a = 0.f;
            #pragma unroll
            for (int d = 0; d < DD; d++) a += Qs[v*DD+d] * Ks[w*DD+d];
            s = a * scale;
        }
        Ss[i] = s;
    }
    __syncthreads();
    if (tid < T2) {
        int v = tid;
        float m = -INFINITY;
        for (int w = 0; w < TT; w++) m = fmaxf(m, Ss[v*TT+w]);
        float sum = 0.f;
        for (int w = 0; w < TT; w++) {
            float e = expf(Ss[v*TT+w] - m);
            Ss[v*TT+w] = e; sum += e;
        }
        float inv = 1.f / sum;
        for (int w = 0; w < TT; w++) Ss[v*TT+w] *= inv;
    }
    __syncthreads();
    for (int i = tid; i < T2*DD; i += 256) {
        int v = i >> 6, d = i & 63;
        float a = 0.f;
        #pragma unroll
        for (int w = 0; w < TT; w++) a += Ss[v*TT+w] * Vs[w*DD+d];
        attbuf[((long long)bn*T2 + v)*HD + h*DD + d] = a;
    }
}

__global__ void add_ln_kernel(float* __restrict__ x, const float* __restrict__ r,
                              const float* __restrict__ g, const float* __restrict__ b)
{
    int row = blockIdx.x;
    int tid = threadIdx.x;
    __shared__ float red[256];
    long long base = (long long)row * HD;
    float v0 = x[base + tid] + r[base + tid];
    float v1 = x[base + tid + 256] + r[base + tid + 256];
    red[tid] = v0 + v1;
    __syncthreads();
    for (int s = 128; s > 0; s >>= 1) { if (tid < s) red[tid] += red[tid+s]; __syncthreads(); }
    float mean = red[0] * (1.f/512.f);
    __syncthreads();
    float d0 = v0 - mean, d1 = v1 - mean;
    red[tid] = d0*d0 + d1*d1;
    __syncthreads();
    for (int s = 128; s > 0; s >>= 1) { if (tid < s) red[tid] += red[tid+s]; __syncthreads(); }
    float rstd = rsqrtf(red[0] * (1.f/512.f) + 1e-5f);
    x[base + tid]       = d0 * rstd * g[tid]       + b[tid];
    x[base + tid + 256] = d1 * rstd * g[tid + 256] + b[tid + 256];
}

__global__ void init_flow_kernel(const float* __restrict__ tv)
{
    int idx = blockIdx.x * blockDim.x + threadIdx.x;
    if (idx >= ROWS*VV) return;
    int bn = idx / (T2*VV);
    int rem = idx - bn * (T2*VV);
    int t2 = rem / VV, v = rem - t2*VV;
    g_u[idx] = tv[((long long)bn*VV + v)*TT + (TT - T2 + t2)];
    g_ld[idx] = 0.f;
}

__global__ void copy_y_kernel()
{
    int idx = blockIdx.x * blockDim.x + threadIdx.x;
    if (idx >= ROWS*INLD) return;
    int row = idx / INLD, col = idx - row*INLD;
    if (col < HD)        g_inp[idx] = g_attv[(long long)row*HD + col];
    else if (col == 515) g_inp[idx] = 0.f;
}

__global__ void write_mu_kernel(int blk)
{
    int idx = blockIdx.x * blockDim.x + threadIdx.x;
    if (idx >= ROWS*VV) return;
    int row = idx / VV, v = idx - row*VV;
    float mask = (float)((v + blk) & 1);
    g_inp[(long long)row * INLD + HD + v] = g_u[idx] * mask;
}

// out3 (both nets) + coupling, fused: one warp per row
__global__ void out3_coupling_kernel(const float* __restrict__ h,
                                     const float* __restrict__ Ws, const float* __restrict__ bs,
                                     const float* __restrict__ Wt, const float* __restrict__ bt,
                                     int blk)
{
    int gw = (blockIdx.x * blockDim.x + threadIdx.x) >> 5;
    int lane = threadIdx.x & 31;
    if (gw >= ROWS) return;
    const float* as = h + (long long)gw * HD;
    const float* at = h + (long long)ROWS*HD + (long long)gw * HD;
    float s0 = 0.f, s1 = 0.f, s2 = 0.f, t0 = 0.f, t1 = 0.f, t2 = 0.f;
    for (int k = lane; k < HD; k += 32) {
        float av = as[k], bv = at[k];
        s0 += av * Ws[k*3 + 0]; s1 += av * Ws[k*3 + 1]; s2 += av * Ws[k*3 + 2];
        t0 += bv * Wt[k*3 + 0]; t1 += bv * Wt[k*3 + 1]; t2 += bv * Wt[k*3 + 2];
    }
    #pragma unroll
    for (int off = 16; off > 0; off >>= 1) {
        s0 += __shfl_down_sync(0xffffffffu, s0, off);
        s1 += __shfl_down_sync(0xffffffffu, s1, off);
        s2 += __shfl_down_sync(0xffffffffu, s2, off);
        t0 += __shfl_down_sync(0xffffffffu, t0, off);
        t1 += __shfl_down_sync(0xffffffffu, t1, off);
        t2 += __shfl_down_sync(0xffffffffu, t2, off);
    }
    if (lane == 0) {
        float sv[3] = {s0 + bs[0], s1 + bs[1], s2 + bs[2]};
        float tv[3] = {t0 + bt[0], t1 + bt[1], t2 + bt[2]};
        #pragma unroll
        for (int v = 0; v < VV; v++) {
            if (((v + blk) & 1) == 0) {
                int idx = gw*3 + v;
                float s = sv[v];
                g_u[idx]  = (g_u[idx] - tv[v]) * expf(-s);
                g_ld[idx] -= s;
            }
        }
    }
}

__global__ void bn_stats_kernel()
{
    int col = blockIdx.x;
    int tid = threadIdx.x;
    __shared__ float rs[256], rq[256];
    float s = 0.f, q = 0.f;
    for (int bn = tid; bn < BNB; bn += 256) {
        float v = g_u[bn*(T2*VV) + col];
        s += v; q += v*v;
    }
    rs[tid] = s; rq[tid] = q;
    __syncthreads();
    for (int st = 128; st > 0; st >>= 1) {
        if (tid < st) { rs[tid] += rs[tid+st]; rq[tid] += rq[tid+st]; }
        __syncthreads();
    }
    if (tid == 0) {
        float m = rs[0] / (float)BNB;
        float var = rq[0] / (float)BNB - m*m;
        g_stats[col] = m;
        g_stats[T2*VV + col] = fmaxf(var, 0.f);
    }
}

// bn apply + write NEXT block's masked mu (fused)
__global__ void bn_apply_kernel(const float* __restrict__ lg,
                                const float* __restrict__ beta, int blk, int write_next)
{
    int idx = blockIdx.x * blockDim.x + threadIdx.x;
    if (idx >= ROWS*VV) return;
    int col = idx % (T2*VV);
    int v = idx % VV;
    float m = g_stats[col];
    float var = g_stats[T2*VV + col];
    float gg = lg[blk*VV + v];
    float be = beta[blk*VV + v];
    float r = rsqrtf(var + 1e-5f);
    float u = expf(gg) * (g_u[idx] - m) * r + be;
    g_u[idx] = u;
    g_ld[idx] += gg - 0.5f * logf(var + 1e-5f);
    if (write_next) {
        float mask = (float)((v + blk + 1) & 1);
        g_inp[(long long)(idx / VV) * INLD + HD + v] = u * mask;
    }
}

__global__ void final_kernel(float* __restrict__ out)
{
    int bn = blockIdx.x * blockDim.x + threadIdx.x;
    if (bn >= BNB) return;
    float acc = 0.f;
    #pragma unroll
    for (int i = 0; i < T2*VV; i++) {
        float u = g_u[bn*(T2*VV) + i];
        acc += 0.5f*u*u + 0.5f*LOG2PI - g_ld[bn*(T2*VV) + i];
    }
    out[bn] = acc;
}

// ---------------- host launcher ----------------
static inline void tcg(const float* A, int lda, long long sA,
                       const float* B, const float* bias, float* C,
                       int M, int N, int Kpad, int Kreal, int act0, int act1,
                       long long sB, long long sBias, long long sC, int Z)
{
    dim3 grid((M + 127)/128, N/128, Z);
    wmma_gemm<<<grid, 256, WM_SMEM>>>(A, lda, sA, B, bias, C,
                                      M, N, Kpad, Kreal, act0, act1, sB, sBias, sC);
}

extern "C" void kernel_launch(void* const* d_in, const int* in_sizes, int n_in,
                              void* d_out, int out_size)
{
    const float* encoded    = (const float*)d_in[0];
    const float* true_value = (const float*)d_in[1];
    const float* W_shift    = (const float*)d_in[2];
    const float* b_shift    = (const float*)d_in[3];
    const float* W_key      = (const float*)d_in[4];
    const float* b_key      = (const float*)d_in[5];
    const float* W_val      = (const float*)d_in[6];
    const float* b_val      = (const float*)d_in[7];
    const float* ln1_s      = (const float*)d_in[8];
    const float* ln1_b      = (const float*)d_in[9];
    const float* ff_w1      = (const float*)d_in[10];
    const float* ff_b1      = (const float*)d_in[11];
    const float* ff_w2      = (const float*)d_in[12];
    const float* ff_b2      = (const float*)d_in[13];
    const float* ln2_s      = (const float*)d_in[14];
    const float* ln2_b      = (const float*)d_in[15];
    const float* s_w_in     = (const float*)d_in[16];
    const float* s_b_in     = (const float*)d_in[17];
    const float* s_w_hid    = (const float*)d_in[18];
    const float* s_b_hid    = (const float*)d_in[19];
    const float* s_w_out    = (const float*)d_in[20];
    const float* s_b_out    = (const float*)d_in[21];
    const float* t_w_in     = (const float*)d_in[22];
    const float* t_b_in     = (const float*)d_in[23];
    const float* t_w_hid    = (const float*)d_in[24];
    const float* t_b_hid    = (const float*)d_in[25];
    const float* t_w_out    = (const float*)d_in[26];
    const float* t_b_out    = (const float*)d_in[27];
    const float* bn_lg      = (const float*)d_in[28];
    const float* bn_be      = (const float*)d_in[29];
    float* out = (float*)d_out;

    cudaFuncSetAttribute(wmma_gemm, cudaFuncAttributeMaxDynamicSharedMemorySize, WM_SMEM);

    float *ev, *wk, *wv, *keys, *vals, *attin, *attv, *attbuf, *f1, *f2, *inp;
    float *hA, *hB, *win, *bin, *whid, *bhid;
    cudaGetSymbolAddress((void**)&ev,     g_ev);
    cudaGetSymbolAddress((void**)&wk,     g_wk);
    cudaGetSymbolAddress((void**)&wv,     g_wv);
    cudaGetSymbolAddress((void**)&keys,   g_keys);
    cudaGetSymbolAddress((void**)&vals,   g_vals);
    cudaGetSymbolAddress((void**)&attin,  g_attin);
    cudaGetSymbolAddress((void**)&attv,   g_attv);
    cudaGetSymbolAddress((void**)&attbuf, g_attbuf);
    cudaGetSymbolAddress((void**)&f1,     g_f1);
    cudaGetSymbolAddress((void**)&f2,     g_f2);
    cudaGetSymbolAddress((void**)&inp,    g_inp);
    cudaGetSymbolAddress((void**)&hA,     g_hA);
    cudaGetSymbolAddress((void**)&hB,     g_hB);
    cudaGetSymbolAddress((void**)&win,    g_win);
    cudaGetSymbolAddress((void**)&bin,    g_bin);
    cudaGetSymbolAddress((void**)&whid,   g_whid);
    cudaGetSymbolAddress((void**)&bhid,   g_bhid);

    {
        int n = LL*DIN*HD;
        transpose_w_kernel<<<(n + 255)/256, 256>>>(W_key, wk);
        transpose_w_kernel<<<(n + 255)/256, 256>>>(W_val, wv);
        int m = BNB*TT*EVLD;
        build_ev_kernel<<<(m + 255)/256, 256>>>(encoded, true_value);
        int q = ROWS*384;
        build_attin_kernel<<<(q + 255)/256, 256>>>(encoded);
        int p1 = NB*2*CY*HD;
        pack_win_kernel<<<(p1 + 255)/256, 256>>>(s_w_in, t_w_in);
        int p2 = NB*2*HD;
        pack_bin_kernel<<<(p2 + 255)/256, 256>>>(s_b_in, t_b_in);
        long long p3 = (long long)NB*NHID*2*HD*HD;
        pack_whid_kernel<<<(int)((p3 + 255)/256), 256>>>(s_w_hid, t_w_hid);
        int p4 = NB*NHID*2*HD;
        pack_bhid_kernel<<<(p4 + 255)/256, 256>>>(s_b_hid, t_b_hid);
    }
    tcg(ev, EVLD, 0, wk, b_key, keys, KVROWS, HD, EVLD, DIN, 0, 0,
        (long long)DIN*HD, HD, (long long)KVROWS*HD, LL);
    tcg(ev, EVLD, 0, wv, b_val, vals, KVROWS, HD, EVLD, DIN, 0, 0,
        (long long)DIN*HD, HD, (long long)KVROWS*HD, LL);
    tcg(attin, 384, 0, W_shift, b_shift, attv, ROWS, HD, 384, 384, 0, 0, 0, 0, 0, 1);
    for (int l = 0; l < LL; l++) {
        attn_kernel<<<dim3(BNB, HH), 256>>>(attv,
            keys + (long long)l*KVROWS*HD,
            vals + (long long)l*KVROWS*HD, attbuf);
        add_ln_kernel<<<ROWS, 256>>>(attv, attbuf, ln1_s + l*HD, ln1_b + l*HD);
        tcg(attv, HD, 0, ff_w1 + (long long)l*HD*HD, ff_b1 + l*HD, f1,
            ROWS, HD, HD, HD, 1, 1, 0, 0, 0, 1);
        tcg(f1, HD, 0, ff_w2 + (long long)l*HD*HD, ff_b2 + l*HD, f2,
            ROWS, HD, HD, HD, 0, 0, 0, 0, 0, 1);
        add_ln_kernel<<<ROWS, 256>>>(attv, f2, ln2_s + l*HD, ln2_b + l*HD);
    }
    {
        int n = ROWS*VV;
        init_flow_kernel<<<(n + 255)/256, 256>>>(true_value);
        int n2 = ROWS*INLD;
        copy_y_kernel<<<(n2 + 255)/256, 256>>>();
        write_mu_kernel<<<(n + 255)/256, 256>>>(0);
    }
    const long long perW = (long long)CY*HD;
    const long long perH = (long long)HD*HD;
    const long long sCh  = (long long)ROWS*HD;
    for (int blk = 0; blk < NB; blk++) {
        tcg(inp, INLD, 0, win + (long long)blk*2*perW, bin + (long long)blk*2*HD, hA,
            ROWS, HD, INLD, CY, 2, 1, perW, HD, sCh, 2);
        float* bufs[5] = {hA, hB, hA, hB, hA};
        for (int i = 0; i < NHID; i++) {
            long long wo = ((long long)(blk*NHID + i))*2;
            tcg(bufs[i], HD, sCh, whid + wo*perH, bhid + wo*HD, bufs[i+1],
                ROWS, HD, HD, HD, 2, 1, perH, HD, sCh, 2);
        }
        out3_coupling_kernel<<<(ROWS*32 + 255)/256, 256>>>(bufs[NHID],
            s_w_out + (long long)blk*HD*VV, s_b_out + blk*VV,
            t_w_out + (long long)blk*HD*VV, t_b_out + blk*VV, blk);
        bn_stats_kernel<<<T2*VV, 256>>>();
        {
            int n = ROWS*VV;
            bn_apply_kernel<<<(n + 255)/256, 256>>>(bn_lg, bn_be, blk, blk + 1 < NB);
        }
    }
    final_kernel<<<(BNB + 255)/256, 256>>>(out);
}

// round 6
// speedup vs baseline: 3.0806x; 1.0487x over previous
#include <cuda_runtime.h>
#include <mma.h>
#include <cstdint>
#include <math.h>

using namespace nvcuda;

// ---------------- problem constants ----------------
#define BNB   650
#define TT    48
#define T2    12
#define VV    3
#define CC    128
#define DIN   387
#define EVLD  388
#define HD    512
#define HH    8
#define DD    64
#define LL    4
#define NB    6
#define NHID  4
#define CY    515
#define INLD  516
#define ROWS  (BNB*T2)     // 7800
#define KVROWS (BNB*TT)    // 31200
#define LOG2PI 1.8378770664093453f

// ---------------- scratch ----------------
__device__ float g_ev[BNB*TT*EVLD];
__device__ float g_wk[LL*DIN*HD];
__device__ float g_wv[LL*DIN*HD];
__device__ float g_wshift[384*HD];
__device__ float g_ffw1[LL*HD*HD];
__device__ float g_ffw2[LL*HD*HD];
__device__ float g_keys[LL*KVROWS*HD];
__device__ float g_vals[LL*KVROWS*HD];
__device__ float g_attin[ROWS*384];
__device__ float g_attv[ROWS*HD];
__device__ float g_attbuf[ROWS*HD];
__device__ float g_f1[ROWS*HD];
__device__ float g_f2[ROWS*HD];
__device__ float g_inp[ROWS*INLD];
__device__ float g_hA[2*ROWS*HD];
__device__ float g_hB[2*ROWS*HD];
__device__ float g_u[ROWS*VV];
__device__ float g_ld[ROWS*VV];
__device__ float g_stats[2*T2*VV];
__device__ float g_win[NB*2*CY*HD];
__device__ float g_bin[NB*2*HD];
__device__ float g_whid[NB*NHID*2*HD*HD];
__device__ float g_bhid[NB*NHID*2*HD];

// round-to-nearest tf32 (so HMMA's truncation is exact afterwards)
__device__ __forceinline__ float to_tf32(float x) {
    float y;
    asm("cvt.rna.tf32.f32 %0, %1;" : "=f"(y) : "f"(x));
    return y;
}

__device__ __forceinline__ float epi_act(float v, int act) {
    if (act == 1) return fmaxf(v, 0.f);
    if (act == 2) return tanhf(v);
    return v;
}

__device__ __forceinline__ void cpa16(uint32_t dst, const float* src, int sz) {
    asm volatile("cp.async.cg.shared.global [%0], [%1], 16, %2;"
                 :: "r"(dst), "l"(src), "r"(sz));
}
__device__ __forceinline__ void cpa_commit() {
    asm volatile("cp.async.commit_group;" ::: "memory");
}

// ---------------- wmma tf32 GEMM: 128 threads, 4 warps of 64x64 -----------
#define ALD 36
#define BLD 132
#define A_STG (128*ALD)
#define B_STG (32*BLD)
#define STG   (A_STG + B_STG)          // 8832 floats / stage
#define NSTAGE 3
#define WM_SMEM (NSTAGE*STG*4)         // 105984 B

__global__ __launch_bounds__(128, 2) void wmma_gemm(
    const float* __restrict__ A, int lda, long long sA,
    const float* __restrict__ B, const float* __restrict__ bias,
    float* __restrict__ C,
    int M, int N, int Kpad, int Kreal, int act0, int act1,
    long long sB, long long sBias, long long sC)
{
    extern __shared__ float sm[];
    long long z = blockIdx.z;
    A    += z * sA;
    B    += z * sB;
    bias += z * sBias;
    C    += z * sC;
    int act = (z == 0) ? act0 : act1;

    int bm = blockIdx.x * 128, bn = blockIdx.y * 128;
    int tid = threadIdx.x, wid = tid >> 5;
    int warp_m = wid >> 1, warp_n = wid & 1;   // 2x2 warps of 64x64

    wmma::fragment<wmma::accumulator, 16, 16, 8, float> acc[4][4];
    #pragma unroll
    for (int i = 0; i < 4; i++)
        #pragma unroll
        for (int j = 0; j < 4; j++) wmma::fill_fragment(acc[i][j], 0.f);

    int nch = (Kpad + 31) >> 5;

    auto load_stage = [&](int s, int c) {
        uint32_t base = (uint32_t)__cvta_generic_to_shared(sm + s * STG);
        uint32_t bBase = base + A_STG * 4;
        int k0 = c << 5;
        #pragma unroll
        for (int it = 0; it < 8; it++) {
            int q = it * 128 + tid;
            int r = q >> 3, kk = (q & 7) << 2;
            int gm = bm + r, gk = k0 + kk;
            int ok = (gm < M && gk < Kpad);
            int cgm = ok ? gm : 0, cgk = ok ? gk : 0;
            cpa16(base + (uint32_t)(r * ALD + kk) * 4,
                  A + (long long)cgm * lda + cgk, ok ? 16 : 0);
        }
        #pragma unroll
        for (int it = 0; it < 8; it++) {
            int q = it * 128 + tid;
            int kk = q >> 5, n = (q & 31) << 2;
            int gk = k0 + kk;
            int ok = (gk < Kreal);
            int cgk = ok ? gk : 0;
            cpa16(bBase + (uint32_t)(kk * BLD + n) * 4,
                  B + (long long)cgk * N + bn + n, ok ? 16 : 0);
        }
    };

    load_stage(0, 0);
    cpa_commit();
    if (nch > 1) { load_stage(1, 1); cpa_commit(); }

    for (int c = 0; c < nch; c++) {
        if (c + 1 < nch) asm volatile("cp.async.wait_group 1;" ::: "memory");
        else             asm volatile("cp.async.wait_group 0;" ::: "memory");
        __syncthreads();
        if (c + 2 < nch) { load_stage((c + 2) % NSTAGE, c + 2); cpa_commit(); }

        float* As = sm + (c % NSTAGE) * STG;
        float* Bs = As + A_STG;
        #pragma unroll
        for (int ks = 0; ks < 4; ks++) {
            int k0 = ks * 8;
            wmma::fragment<wmma::matrix_a, 16, 16, 8, wmma::precision::tf32, wmma::row_major> af[4];
            wmma::fragment<wmma::matrix_b, 16, 16, 8, wmma::precision::tf32, wmma::row_major> bf[4];
            #pragma unroll
            for (int i = 0; i < 4; i++)
                wmma::load_matrix_sync(af[i], As + (warp_m*64 + i*16) * ALD + k0, ALD);
            #pragma unroll
            for (int j = 0; j < 4; j++)
                wmma::load_matrix_sync(bf[j], Bs + k0 * BLD + warp_n*64 + j*16, BLD);
            // operands are pre-rounded to tf32 in memory; HW truncation is exact
            #pragma unroll
            for (int i = 0; i < 4; i++)
                #pragma unroll
                for (int j = 0; j < 4; j++)
                    wmma::mma_sync(acc[i][j], af[i], bf[j], acc[i][j]);
        }
    }
    __syncthreads();

    float* Cs = sm;
    #pragma unroll
    for (int i = 0; i < 4; i++)
        #pragma unroll
        for (int j = 0; j < 4; j++)
            wmma::store_matrix_sync(Cs + (warp_m*64 + i*16) * BLD + warp_n*64 + j*16,
                                    acc[i][j], BLD, wmma::mem_row_major);
    __syncthreads();

    #pragma unroll
    for (int it = 0; it < 32; it++) {
        int idx = it * 128 + tid;
        int r = idx >> 5, c4 = (idx & 31) * 4;
        int gm = bm + r;
        if (gm >= M) continue;
        int gc = bn + c4;
        float4 v;
        v.x = to_tf32(epi_act(Cs[r * BLD + c4 + 0] + bias[gc + 0], act));
        v.y = to_tf32(epi_act(Cs[r * BLD + c4 + 1] + bias[gc + 1], act));
        v.z = to_tf32(epi_act(Cs[r * BLD + c4 + 2] + bias[gc + 2], act));
        v.w = to_tf32(epi_act(Cs[r * BLD + c4 + 3] + bias[gc + 3], act));
        *(float4*)(C + (long long)gm * N + gc) = v;
    }
}

// ---------------- pack / round kernels ----------------
__global__ void roundcopy_kernel(const float* __restrict__ src, float* __restrict__ dst,
                                 long long n)
{
    long long idx = (long long)blockIdx.x * blockDim.x + threadIdx.x;
    if (idx < n) dst[idx] = to_tf32(src[idx]);
}
__global__ void pack_win_kernel(const float* __restrict__ s, const float* __restrict__ t)
{
    int idx = blockIdx.x * blockDim.x + threadIdx.x;
    const int per = CY*HD;
    if (idx >= NB*2*per) return;
    int blk = idx / (2*per);
    int r = idx - blk*2*per;
    int net = r / per, off = r - net*per;
    g_win[idx] = to_tf32(net ? t[(long long)blk*per + off] : s[(long long)blk*per + off]);
}
__global__ void pack_bin_kernel(const float* __restrict__ s, const float* __restrict__ t)
{
    int idx = blockIdx.x * blockDim.x + threadIdx.x;
    if (idx >= NB*2*HD) return;
    int blk = idx / (2*HD);
    int r = idx - blk*2*HD;
    int net = r / HD, off = r - net*HD;
    g_bin[idx] = net ? t[blk*HD + off] : s[blk*HD + off];
}
__global__ void pack_whid_kernel(const float* __restrict__ s, const float* __restrict__ t)
{
    long long idx = (long long)blockIdx.x * blockDim.x + threadIdx.x;
    const long long per = HD*HD;
    if (idx >= (long long)NB*NHID*2*per) return;
    long long u = idx / (2*per);
    long long r = idx - u*2*per;
    int net = (int)(r / per);
    long long off = r - (long long)net*per;
    g_whid[idx] = to_tf32(net ? t[u*per + off] : s[u*per + off]);
}
__global__ void pack_bhid_kernel(const float* __restrict__ s, const float* __restrict__ t)
{
    int idx = blockIdx.x * blockDim.x + threadIdx.x;
    if (idx >= NB*NHID*2*HD) return;
    int u = idx / (2*HD);
    int r = idx - u*2*HD;
    int net = r / HD, off = r - net*HD;
    g_bhid[idx] = net ? t[u*HD + off] : s[u*HD + off];
}

// ---------------- small kernels ----------------
__global__ void transpose_w_kernel(const float* __restrict__ W, float* __restrict__ out)
{
    int idx = blockIdx.x * blockDim.x + threadIdx.x;
    if (idx >= LL*DIN*HD) return;
    int l = idx / (DIN*HD);
    int rem = idx - l * (DIN*HD);
    int e = rem / HD;
    int n = rem - e * HD;
    int h = n >> 6, d = n & 63;
    out[idx] = to_tf32(W[(((long long)l*HH + h)*DIN + e)*DD + d]);
}

__global__ void build_ev_kernel(const float* __restrict__ encoded,
                                const float* __restrict__ tv)
{
    int idx = blockIdx.x * blockDim.x + threadIdx.x;
    if (idx >= BNB*TT*EVLD) return;
    int bn = idx / (TT*EVLD);
    int rem = idx - bn * (TT*EVLD);
    int t = rem / EVLD;
    int e = rem - t * EVLD;
    float val = 0.f;
    if (e < DIN) {
        int v = e / (CC+1);
        int j = e - v * (CC+1);
        if (j < CC) val = encoded[(((long long)bn*VV + v)*TT + t)*CC + j];
        else        val = tv[((long long)bn*VV + v)*TT + t];
    }
    g_ev[idx] = to_tf32(val);
}

__global__ void build_attin_kernel(const float* __restrict__ encoded)
{
    int idx = blockIdx.x * blockDim.x + threadIdx.x;
    if (idx >= ROWS*384) return;
    int row = idx / 384;
    int col = idx - row*384;
    int bn = row / T2, t2 = row - bn*T2;
    int v = col >> 7, j = col & 127;
    g_attin[idx] = to_tf32(encoded[(((long long)bn*VV + v)*TT + (TT - T2 + t2))*CC + j]);
}

__global__ void attn_kernel(const float* __restrict__ attv,
                            const float* __restrict__ keys_l,
                            const float* __restrict__ vals_l,
                            float* __restrict__ attbuf)
{
    int bn = blockIdx.x, h = blockIdx.y;
    __shared__ float Qs[T2*DD];
    __shared__ float Ks[TT*DD];
    __shared__ float Vs[TT*DD];
    __shared__ float Ss[T2*TT];
    int tid = threadIdx.x;
    const float* kb = keys_l + (long long)bn*TT*HD + h*DD;
    const float* vb = vals_l + (long long)bn*TT*HD + h*DD;
    for (int i = tid; i < TT*DD; i += 256) {
        int t = i >> 6, d = i & 63;
        Ks[i] = kb[(long long)t*HD + d];
        Vs[i] = vb[(long long)t*HD + d];
    }
    for (int i = tid; i < T2*DD; i += 256) {
        int v = i >> 6, d = i & 63;
        Qs[i] = attv[((long long)bn*T2 + v)*HD + h*DD + d];
    }
    __syncthreads();
    const float scale = 0.125f;
    for (int i = tid; i < T2*TT; i += 256) {
        int v = i / TT, w = i - v*TT;
        float s;
        if (w >= (TT - T2) + v) s = -INFINITY;
        else {
            float a = 0.f;
            #pragma unroll
            for (int d = 0; d < DD; d++) a += Qs[v*DD+d] * Ks[w*DD+d];
            s = a * scale;
        }
        Ss[i] = s;
    }
    __syncthreads();
    if (tid < T2) {
        int v = tid;
        float m = -INFINITY;
        for (int w = 0; w < TT; w++) m = fmaxf(m, Ss[v*TT+w]);
        float sum = 0.f;
        for (int w = 0; w < TT; w++) {
            float e = expf(Ss[v*TT+w] - m);
            Ss[v*TT+w] = e; sum += e;
        }
        float inv = 1.f / sum;
        for (int w = 0; w < TT; w++) Ss[v*TT+w] *= inv;
    }
    __syncthreads();
    for (int i = tid; i < T2*DD; i += 256) {
        int v = i >> 6, d = i & 63;
        float a = 0.f;
        #pragma unroll
        for (int w = 0; w < TT; w++) a += Ss[v*TT+w] * Vs[w*DD+d];
        attbuf[((long long)bn*T2 + v)*HD + h*DD + d] = a;
    }
}

__global__ void add_ln_kernel(float* __restrict__ x, const float* __restrict__ r,
                              const float* __restrict__ g, const float* __restrict__ b)
{
    int row = blockIdx.x;
    int tid = threadIdx.x;
    __shared__ float red[256];
    long long base = (long long)row * HD;
    float v0 = x[base + tid] + r[base + tid];
    float v1 = x[base + tid + 256] + r[base + tid + 256];
    red[tid] = v0 + v1;
    __syncthreads();
    for (int s = 128; s > 0; s >>= 1) { if (tid < s) red[tid] += red[tid+s]; __syncthreads(); }
    float mean = red[0] * (1.f/512.f);
    __syncthreads();
    float d0 = v0 - mean, d1 = v1 - mean;
    red[tid] = d0*d0 + d1*d1;
    __syncthreads();
    for (int s = 128; s > 0; s >>= 1) { if (tid < s) red[tid] += red[tid+s]; __syncthreads(); }
    float rstd = rsqrtf(red[0] * (1.f/512.f) + 1e-5f);
    x[base + tid]       = to_tf32(d0 * rstd * g[tid]       + b[tid]);
    x[base + tid + 256] = to_tf32(d1 * rstd * g[tid + 256] + b[tid + 256]);
}

__global__ void init_flow_kernel(const float* __restrict__ tv)
{
    int idx = blockIdx.x * blockDim.x + threadIdx.x;
    if (idx >= ROWS*VV) return;
    int bn = idx / (T2*VV);
    int rem = idx - bn * (T2*VV);
    int t2 = rem / VV, v = rem - t2*VV;
    g_u[idx] = tv[((long long)bn*VV + v)*TT + (TT - T2 + t2)];
    g_ld[idx] = 0.f;
}

__global__ void copy_y_kernel()
{
    int idx = blockIdx.x * blockDim.x + threadIdx.x;
    if (idx >= ROWS*INLD) return;
    int row = idx / INLD, col = idx - row*INLD;
    if (col < HD)        g_inp[idx] = g_attv[(long long)row*HD + col];
    else if (col == 515) g_inp[idx] = 0.f;
}

__global__ void write_mu_kernel(int blk)
{
    int idx = blockIdx.x * blockDim.x + threadIdx.x;
    if (idx >= ROWS*VV) return;
    int row = idx / VV, v = idx - row*VV;
    float mask = (float)((v + blk) & 1);
    g_inp[(long long)row * INLD + HD + v] = to_tf32(g_u[idx] * mask);
}

// out3 (both nets) + coupling, fused
__global__ void out3_coupling_kernel(const float* __restrict__ h,
                                     const float* __restrict__ Ws, const float* __restrict__ bs,
                                     const float* __restrict__ Wt, const float* __restrict__ bt,
                                     int blk)
{
    int gw = (blockIdx.x * blockDim.x + threadIdx.x) >> 5;
    int lane = threadIdx.x & 31;
    if (gw >= ROWS) return;
    const float* as = h + (long long)gw * HD;
    const float* at = h + (long long)ROWS*HD + (long long)gw * HD;
    float s0 = 0.f, s1 = 0.f, s2 = 0.f, t0 = 0.f, t1 = 0.f, t2 = 0.f;
    for (int k = lane; k < HD; k += 32) {
        float av = as[k], bv = at[k];
        s0 += av * Ws[k*3 + 0]; s1 += av * Ws[k*3 + 1]; s2 += av * Ws[k*3 + 2];
        t0 += bv * Wt[k*3 + 0]; t1 += bv * Wt[k*3 + 1]; t2 += bv * Wt[k*3 + 2];
    }
    #pragma unroll
    for (int off = 16; off > 0; off >>= 1) {
        s0 += __shfl_down_sync(0xffffffffu, s0, off);
        s1 += __shfl_down_sync(0xffffffffu, s1, off);
        s2 += __shfl_down_sync(0xffffffffu, s2, off);
        t0 += __shfl_down_sync(0xffffffffu, t0, off);
        t1 += __shfl_down_sync(0xffffffffu, t1, off);
        t2 += __shfl_down_sync(0xffffffffu, t2, off);
    }
    if (lane == 0) {
        float sv[3] = {s0 + bs[0], s1 + bs[1], s2 + bs[2]};
        float tv[3] = {t0 + bt[0], t1 + bt[1], t2 + bt[2]};
        #pragma unroll
        for (int v = 0; v < VV; v++) {
            if (((v + blk) & 1) == 0) {
                int idx = gw*3 + v;
                float s = sv[v];
                g_u[idx]  = (g_u[idx] - tv[v]) * expf(-s);
                g_ld[idx] -= s;
            }
        }
    }
}

__global__ void bn_stats_kernel()
{
    int col = blockIdx.x;
    int tid = threadIdx.x;
    __shared__ float rs[256], rq[256];
    float s = 0.f, q = 0.f;
    for (int bn = tid; bn < BNB; bn += 256) {
        float v = g_u[bn*(T2*VV) + col];
        s += v; q += v*v;
    }
    rs[tid] = s; rq[tid] = q;
    __syncthreads();
    for (int st = 128; st > 0; st >>= 1) {
        if (tid < st) { rs[tid] += rs[tid+st]; rq[tid] += rq[tid+st]; }
        __syncthreads();
    }
    if (tid == 0) {
        float m = rs[0] / (float)BNB;
        float var = rq[0] / (float)BNB - m*m;
        g_stats[col] = m;
        g_stats[T2*VV + col] = fmaxf(var, 0.f);
    }
}

__global__ void bn_apply_kernel(const float* __restrict__ lg,
                                const float* __restrict__ beta, int blk, int write_next)
{
    int idx = blockIdx.x * blockDim.x + threadIdx.x;
    if (idx >= ROWS*VV) return;
    int col = idx % (T2*VV);
    int v = idx % VV;
    float m = g_stats[col];
    float var = g_stats[T2*VV + col];
    float gg = lg[blk*VV + v];
    float be = beta[blk*VV + v];
    float r = rsqrtf(var + 1e-5f);
    float u = expf(gg) * (g_u[idx] - m) * r + be;
    g_u[idx] = u;
    g_ld[idx] += gg - 0.5f * logf(var + 1e-5f);
    if (write_next) {
        float mask = (float)((v + blk + 1) & 1);
        g_inp[(long long)(idx / VV) * INLD + HD + v] = to_tf32(u * mask);
    }
}

__global__ void final_kernel(float* __restrict__ out)
{
    int bn = blockIdx.x * blockDim.x + threadIdx.x;
    if (bn >= BNB) return;
    float acc = 0.f;
    #pragma unroll
    for (int i = 0; i < T2*VV; i++) {
        float u = g_u[bn*(T2*VV) + i];
        acc += 0.5f*u*u + 0.5f*LOG2PI - g_ld[bn*(T2*VV) + i];
    }
    out[bn] = acc;
}

// ---------------- host launcher ----------------
static inline void tcg(const float* A, int lda, long long sA,
                       const float* B, const float* bias, float* C,
                       int M, int N, int Kpad, int Kreal, int act0, int act1,
                       long long sB, long long sBias, long long sC, int Z)
{
    dim3 grid((M + 127)/128, N/128, Z);
    wmma_gemm<<<grid, 128, WM_SMEM>>>(A, lda, sA, B, bias, C,
                                      M, N, Kpad, Kreal, act0, act1, sB, sBias, sC);
}

extern "C" void kernel_launch(void* const* d_in, const int* in_sizes, int n_in,
                              void* d_out, int out_size)
{
    const float* encoded    = (const float*)d_in[0];
    const float* true_value = (const float*)d_in[1];
    const float* W_shift    = (const float*)d_in[2];
    const float* b_shift    = (const float*)d_in[3];
    const float* W_key      = (const float*)d_in[4];
    const float* b_key      = (const float*)d_in[5];
    const float* W_val      = (const float*)d_in[6];
    const float* b_val      = (const float*)d_in[7];
    const float* ln1_s      = (const float*)d_in[8];
    const float* ln1_b      = (const float*)d_in[9];
    const float* ff_w1      = (const float*)d_in[10];
    const float* ff_b1      = (const float*)d_in[11];
    const float* ff_w2      = (const float*)d_in[12];
    const float* ff_b2      = (const float*)d_in[13];
    const float* ln2_s      = (const float*)d_in[14];
    const float* ln2_b      = (const float*)d_in[15];
    const float* s_w_in     = (const float*)d_in[16];
    const float* s_b_in     = (const float*)d_in[17];
    const float* s_w_hid    = (const float*)d_in[18];
    const float* s_b_hid    = (const float*)d_in[19];
    const float* s_w_out    = (const float*)d_in[20];
    const float* s_b_out    = (const float*)d_in[21];
    const float* t_w_in     = (const float*)d_in[22];
    const float* t_b_in     = (const float*)d_in[23];
    const float* t_w_hid    = (const float*)d_in[24];
    const float* t_b_hid    = (const float*)d_in[25];
    const float* t_w_out    = (const float*)d_in[26];
    const float* t_b_out    = (const float*)d_in[27];
    const float* bn_lg      = (const float*)d_in[28];
    const float* bn_be      = (const float*)d_in[29];
    float* out = (float*)d_out;

    cudaFuncSetAttribute(wmma_gemm, cudaFuncAttributeMaxDynamicSharedMemorySize, WM_SMEM);

    float *ev, *wk, *wv, *wshift, *ffw1, *ffw2, *keys, *vals, *attin, *attv, *attbuf, *f1, *f2, *inp;
    float *hA, *hB, *win, *bin, *whid, *bhid;
    cudaGetSymbolAddress((void**)&ev,     g_ev);
    cudaGetSymbolAddress((void**)&wk,     g_wk);
    cudaGetSymbolAddress((void**)&wv,     g_wv);
    cudaGetSymbolAddress((void**)&wshift, g_wshift);
    cudaGetSymbolAddress((void**)&ffw1,   g_ffw1);
    cudaGetSymbolAddress((void**)&ffw2,   g_ffw2);
    cudaGetSymbolAddress((void**)&keys,   g_keys);
    cudaGetSymbolAddress((void**)&vals,   g_vals);
    cudaGetSymbolAddress((void**)&attin,  g_attin);
    cudaGetSymbolAddress((void**)&attv,   g_attv);
    cudaGetSymbolAddress((void**)&attbuf, g_attbuf);
    cudaGetSymbolAddress((void**)&f1,     g_f1);
    cudaGetSymbolAddress((void**)&f2,     g_f2);
    cudaGetSymbolAddress((void**)&inp,    g_inp);
    cudaGetSymbolAddress((void**)&hA,     g_hA);
    cudaGetSymbolAddress((void**)&hB,     g_hB);
    cudaGetSymbolAddress((void**)&win,    g_win);
    cudaGetSymbolAddress((void**)&bin,    g_bin);
    cudaGetSymbolAddress((void**)&whid,   g_whid);
    cudaGetSymbolAddress((void**)&bhid,   g_bhid);

    {
        int n = LL*DIN*HD;
        transpose_w_kernel<<<(n + 255)/256, 256>>>(W_key, wk);
        transpose_w_kernel<<<(n + 255)/256, 256>>>(W_val, wv);
        long long nw = 384*HD;
        roundcopy_kernel<<<(int)((nw + 255)/256), 256>>>(W_shift, wshift, nw);
        long long nf = (long long)LL*HD*HD;
        roundcopy_kernel<<<(int)((nf + 255)/256), 256>>>(ff_w1, ffw1, nf);
        roundcopy_kernel<<<(int)((nf + 255)/256), 256>>>(ff_w2, ffw2, nf);
        int m = BNB*TT*EVLD;
        build_ev_kernel<<<(m + 255)/256, 256>>>(encoded, true_value);
        int q = ROWS*384;
        build_attin_kernel<<<(q + 255)/256, 256>>>(encoded);
        int p1 = NB*2*CY*HD;
        pack_win_kernel<<<(p1 + 255)/256, 256>>>(s_w_in, t_w_in);
        int p2 = NB*2*HD;
        pack_bin_kernel<<<(p2 + 255)/256, 256>>>(s_b_in, t_b_in);
        long long p3 = (long long)NB*NHID*2*HD*HD;
        pack_whid_kernel<<<(int)((p3 + 255)/256), 256>>>(s_w_hid, t_w_hid);
        int p4 = NB*NHID*2*HD;
        pack_bhid_kernel<<<(p4 + 255)/256, 256>>>(s_b_hid, t_b_hid);
    }
    tcg(ev, EVLD, 0, wk, b_key, keys, KVROWS, HD, EVLD, DIN, 0, 0,
        (long long)DIN*HD, HD, (long long)KVROWS*HD, LL);
    tcg(ev, EVLD, 0, wv, b_val, vals, KVROWS, HD, EVLD, DIN, 0, 0,
        (long long)DIN*HD, HD, (long long)KVROWS*HD, LL);
    tcg(attin, 384, 0, wshift, b_shift, attv, ROWS, HD, 384, 384, 0, 0, 0, 0, 0, 1);
    for (int l = 0; l < LL; l++) {
        attn_kernel<<<dim3(BNB, HH), 256>>>(attv,
            keys + (long long)l*KVROWS*HD,
            vals + (long long)l*KVROWS*HD, attbuf);
        add_ln_kernel<<<ROWS, 256>>>(attv, attbuf, ln1_s + l*HD, ln1_b + l*HD);
        tcg(attv, HD, 0, ffw1 + (long long)l*HD*HD, ff_b1 + l*HD, f1,
            ROWS, HD, HD, HD, 1, 1, 0, 0, 0, 1);
        tcg(f1, HD, 0, ffw2 + (long long)l*HD*HD, ff_b2 + l*HD, f2,
            ROWS, HD, HD, HD, 0, 0, 0, 0, 0, 1);
        add_ln_kernel<<<ROWS, 256>>>(attv, f2, ln2_s + l*HD, ln2_b + l*HD);
    }
    {
        int n = ROWS*VV;
        init_flow_kernel<<<(n + 255)/256, 256>>>(true_value);
        int n2 = ROWS*INLD;
        copy_y_kernel<<<(n2 + 255)/256, 256>>>();
        write_mu_kernel<<<(n + 255)/256, 256>>>(0);
    }
    const long long perW = (long long)CY*HD;
    const long long perH = (long long)HD*HD;
    const long long sCh  = (long long)ROWS*HD;
    for (int blk = 0; blk < NB; blk++) {
        tcg(inp, INLD, 0, win + (long long)blk*2*perW, bin + (long long)blk*2*HD, hA,
            ROWS, HD, INLD, CY, 2, 1, perW, HD, sCh, 2);
        float* bufs[5] = {hA, hB, hA, hB, hA};
        for (int i = 0; i < NHID; i++) {
            long long wo = ((long long)(blk*NHID + i))*2;
            tcg(bufs[i], HD, sCh, whid + wo*perH, bhid + wo*HD, bufs[i+1],
                ROWS, HD, HD, HD, 2, 1, perH, HD, sCh, 2);
        }
        out3_coupling_kernel<<<(ROWS*32 + 255)/256, 256>>>(bufs[NHID],
            s_w_out + (long long)blk*HD*VV, s_b_out + blk*VV,
            t_w_out + (long long)blk*HD*VV, t_b_out + blk*VV, blk);
        bn_stats_kernel<<<T2*VV, 256>>>();
        {
            int n = ROWS*VV;
            bn_apply_kernel<<<(n + 255)/256, 256>>>(bn_lg, bn_be, blk, blk + 1 < NB);
        }
    }
    final_kernel<<<(BNB + 255)/256, 256>>>(out);
}